// round 1
// baseline (speedup 1.0000x reference)
#include <cuda_runtime.h>
#include <cstdint>

#define BSZ   16
#define NN    1024
#define HIDD  64
#define DD    128      // 2*HID
#define CC    256      // F + D
#define PREK  4

#define XSZ   (BSZ * NN * CC)      // 4,194,304 per hop array
#define OUT0  (BSZ * NN * DD)      // 2,097,152  (start of new_hidden in d_out)

// phase scale = PI / (EMB_RANGE / PI) ... careful: phase = R / (EMB_RANGE/PI) = R * PI/EMB_RANGE
// EMB_RANGE = 14.0/64 = 0.21875
#define PHASE_SCALE ((float)(3.141592653589793 / 0.21875))

// ---------------- scratch (static device allocations; no cudaMalloc) ----------
__device__ float g_x[PREK][XSZ];          // x0..x3  (67 MB)
__device__ float g_wt[1024 * 128];        // gc_w re-laid: wt[(m*256+c)*128 + d] = gc_w[d*1024 + c*4 + m]
__device__ float g_gco[BSZ * NN * DD];    // conv_out (post leaky-relu)
__device__ float g_cos[PREK * NN * HIDD];
__device__ float g_sin[PREK * NN * HIDD];
__device__ float g_att[BSZ * NN * DD];
__device__ float g_sa[BSZ * PREK];
__device__ float g_wa[BSZ * PREK];

// ---------------- build x0 = conv_in -----------------------------------------
__global__ __launch_bounds__(256) void k_build_x0(const float* __restrict__ inputs,
                                                  const float* __restrict__ hidden)
{
    int idx = blockIdx.x * 256 + threadIdx.x;
    if (idx >= XSZ) return;
    int c = idx & 255;
    int n = (idx >> 8) & 1023;
    int b = idx >> 18;
    float v;
    if (c < 64) {
        v = inputs[((size_t)(b * NN + n)) * 128 + c];                       // re_in
    } else if (c < 128) {
        v = hidden[(((size_t)(b * 4 + 3) * NN + n)) * 128 + (c - 64)];      // re_p
    } else if (c < 192) {
        v = inputs[((size_t)(b * NN + n)) * 128 + (c - 128 + 64)];          // im_in
    } else {
        v = hidden[(((size_t)(b * 4 + 3) * NN + n)) * 128 + (c - 192 + 64)];// im_p
    }
    g_x[0][idx] = v;
}

// ---------------- re-layout gc_w ----------------------------------------------
__global__ __launch_bounds__(256) void k_wt(const float* __restrict__ gc_w)
{
    int i = blockIdx.x * 256 + threadIdx.x;   // i over 1024*128
    if (i >= 1024 * 128) return;
    int d  = i & 127;
    int kk = i >> 7;          // m*256 + c
    int m  = kk >> 8;
    int c  = kk & 255;
    g_wt[i] = gc_w[(size_t)d * 1024 + c * 4 + m];
}

// ---------------- cos/sin tables ----------------------------------------------
__global__ __launch_bounds__(256) void k_cs(const float* __restrict__ R)
{
    int i = blockIdx.x * 256 + threadIdx.x;
    if (i >= PREK * NN * HIDD) return;
    float ph = R[i] * PHASE_SCALE;
    float s, c;
    sincosf(ph, &s, &c);
    g_cos[i] = c;
    g_sin[i] = s;
}

// ---------------- Chebyshev GEMM: Y = S @ X  (epilogue 2*acc - prev) ----------
// BM=128 BN=128 BK=16, 256 threads, 8x8 microtile
__global__ __launch_bounds__(256) void k_cheb(const float* __restrict__ S, int hop)
{
    const float* X = g_x[hop];
    float* Y = g_x[hop + 1];
    const float* P = (hop >= 1) ? g_x[hop - 1] : nullptr;

    const int b    = blockIdx.z;
    const int col0 = blockIdx.x * 128;
    const int row0 = blockIdx.y * 128;
    const float* Sb = S + (size_t)b * NN * NN;
    const float* Xb = X + (size_t)b * NN * CC;
    float* Yb = Y + (size_t)b * NN * CC;

    __shared__ float As[16][132];
    __shared__ float Bs[16][132];

    const int tid = threadIdx.x;
    const int a_r = tid >> 2;
    const int a_c = (tid & 3) << 2;
    const int b_r = tid >> 5;
    const int b_c = (tid & 31) << 2;
    const int ty  = tid >> 4;
    const int tx  = tid & 15;

    float acc[8][8];
#pragma unroll
    for (int i = 0; i < 8; i++)
#pragma unroll
        for (int j = 0; j < 8; j++) acc[i][j] = 0.f;

    for (int k0 = 0; k0 < NN; k0 += 16) {
        float4 a0 = *(const float4*)(Sb + (size_t)(row0 + a_r) * NN + k0 + a_c);
        float4 a1 = *(const float4*)(Sb + (size_t)(row0 + a_r + 64) * NN + k0 + a_c);
        float4 b0 = *(const float4*)(Xb + (size_t)(k0 + b_r) * CC + col0 + b_c);
        float4 b1 = *(const float4*)(Xb + (size_t)(k0 + b_r + 8) * CC + col0 + b_c);
        __syncthreads();
        As[a_c + 0][a_r] = a0.x; As[a_c + 1][a_r] = a0.y;
        As[a_c + 2][a_r] = a0.z; As[a_c + 3][a_r] = a0.w;
        As[a_c + 0][a_r + 64] = a1.x; As[a_c + 1][a_r + 64] = a1.y;
        As[a_c + 2][a_r + 64] = a1.z; As[a_c + 3][a_r + 64] = a1.w;
        *(float4*)&Bs[b_r][b_c]     = b0;
        *(float4*)&Bs[b_r + 8][b_c] = b1;
        __syncthreads();
#pragma unroll
        for (int kk = 0; kk < 16; kk++) {
            float ar[8], br[8];
            *(float4*)&ar[0] = *(const float4*)&As[kk][ty * 8];
            *(float4*)&ar[4] = *(const float4*)&As[kk][ty * 8 + 4];
            *(float4*)&br[0] = *(const float4*)&Bs[kk][tx * 8];
            *(float4*)&br[4] = *(const float4*)&Bs[kk][tx * 8 + 4];
#pragma unroll
            for (int i = 0; i < 8; i++)
#pragma unroll
                for (int j = 0; j < 8; j++) acc[i][j] += ar[i] * br[j];
        }
    }

#pragma unroll
    for (int i = 0; i < 8; i++) {
        int row = row0 + ty * 8 + i;
        size_t off = (size_t)row * CC + col0 + tx * 8;
        if (hop == 0) {
            float4 v0 = make_float4(acc[i][0], acc[i][1], acc[i][2], acc[i][3]);
            float4 v1 = make_float4(acc[i][4], acc[i][5], acc[i][6], acc[i][7]);
            *(float4*)(Yb + off)     = v0;
            *(float4*)(Yb + off + 4) = v1;
        } else {
            const float* pp = P + (size_t)b * NN * CC + off;
            float4 p0 = *(const float4*)(pp);
            float4 p1 = *(const float4*)(pp + 4);
            float4 v0 = make_float4(2.f * acc[i][0] - p0.x, 2.f * acc[i][1] - p0.y,
                                    2.f * acc[i][2] - p0.z, 2.f * acc[i][3] - p0.w);
            float4 v1 = make_float4(2.f * acc[i][4] - p1.x, 2.f * acc[i][5] - p1.y,
                                    2.f * acc[i][6] - p1.z, 2.f * acc[i][7] - p1.w);
            *(float4*)(Yb + off)     = v0;
            *(float4*)(Yb + off + 4) = v1;
        }
    }
}

// ---------------- gco GEMM: (16384 x 1024) @ (1024 x 128), K over 4 hop arrays
// BM=64 BN=128 BK=16, 256 threads, 4x8 microtile; epilogue +gc_b, leaky relu
__global__ __launch_bounds__(256) void k_gemm2(const float* __restrict__ gc_b)
{
    const int row0 = blockIdx.x * 64;

    __shared__ float As[16][68];
    __shared__ float Bs[16][132];

    const int tid = threadIdx.x;
    const int a_r = tid >> 2;
    const int a_c = (tid & 3) << 2;
    const int b_r = tid >> 5;
    const int b_c = (tid & 31) << 2;
    const int ty  = tid >> 4;
    const int tx  = tid & 15;

    float acc[4][8];
#pragma unroll
    for (int i = 0; i < 4; i++)
#pragma unroll
        for (int j = 0; j < 8; j++) acc[i][j] = 0.f;

    for (int k0 = 0; k0 < 1024; k0 += 16) {
        const int m  = k0 >> 8;
        const int c0 = k0 & 255;
        float4 av = *(const float4*)(&g_x[m][0] + (size_t)(row0 + a_r) * CC + c0 + a_c);
        float4 b0 = *(const float4*)(g_wt + (size_t)(k0 + b_r) * 128 + b_c);
        float4 b1 = *(const float4*)(g_wt + (size_t)(k0 + b_r + 8) * 128 + b_c);
        __syncthreads();
        As[a_c + 0][a_r] = av.x; As[a_c + 1][a_r] = av.y;
        As[a_c + 2][a_r] = av.z; As[a_c + 3][a_r] = av.w;
        *(float4*)&Bs[b_r][b_c]     = b0;
        *(float4*)&Bs[b_r + 8][b_c] = b1;
        __syncthreads();
#pragma unroll
        for (int kk = 0; kk < 16; kk++) {
            float ar[4], br[8];
            *(float4*)&ar[0] = *(const float4*)&As[kk][ty * 4];
            *(float4*)&br[0] = *(const float4*)&Bs[kk][tx * 8];
            *(float4*)&br[4] = *(const float4*)&Bs[kk][tx * 8 + 4];
#pragma unroll
            for (int i = 0; i < 4; i++)
#pragma unroll
                for (int j = 0; j < 8; j++) acc[i][j] += ar[i] * br[j];
        }
    }

#pragma unroll
    for (int i = 0; i < 4; i++) {
        int rr = row0 + ty * 4 + i;
#pragma unroll
        for (int j = 0; j < 8; j++) {
            int col = tx * 8 + j;
            float v = acc[i][j] + gc_b[col];
            v = (v >= 0.f) ? v : 0.01f * v;
            g_gco[(size_t)rr * 128 + col] = v;
        }
    }
}

// ---------------- sa[b,k] reduction -------------------------------------------
__global__ __launch_bounds__(256) void k_sa(const float* __restrict__ hidden,
                                            const float* __restrict__ att_w,
                                            const float* __restrict__ att_b)
{
    const int k = blockIdx.x;
    const int b = blockIdx.y;
    const float* hb = hidden + ((size_t)(b * 4 + k) << 17);   // *N*D
    const int tid = threadIdx.x;

    float sum = 0.f;
    for (int i = tid; i < NN * HIDD; i += 256) {
        int n = i >> 6, h = i & 63;
        float re = hb[(n << 7) + h];
        float im = hb[(n << 7) + 64 + h];
        float c = g_cos[(k << 16) + i];
        float s = g_sin[(k << 16) + i];
        sum += (c * re - s * im) * att_w[(n << 7) + h]
             + (s * re + c * im) * att_w[(n << 7) + 64 + h];
    }
    __shared__ float red[8];
    for (int o = 16; o; o >>= 1) sum += __shfl_down_sync(0xffffffffu, sum, o);
    if ((tid & 31) == 0) red[tid >> 5] = sum;
    __syncthreads();
    if (tid < 8) {
        float v = red[tid];
        for (int o = 4; o; o >>= 1) v += __shfl_down_sync(0xffu, v, o);
        if (tid == 0) g_sa[b * 4 + k] = v + att_b[0];
    }
}

// ---------------- softmax over k=4 per batch ----------------------------------
__global__ void k_softmax()
{
    int b = threadIdx.x;
    if (b >= BSZ) return;
    float s0 = g_sa[b * 4 + 0], s1 = g_sa[b * 4 + 1];
    float s2 = g_sa[b * 4 + 2], s3 = g_sa[b * 4 + 3];
    float m = fmaxf(fmaxf(s0, s1), fmaxf(s2, s3));
    float e0 = expf(s0 - m), e1 = expf(s1 - m), e2 = expf(s2 - m), e3 = expf(s3 - m);
    float inv = 1.f / (e0 + e1 + e2 + e3);
    g_wa[b * 4 + 0] = e0 * inv;
    g_wa[b * 4 + 1] = e1 * inv;
    g_wa[b * 4 + 2] = e2 * inv;
    g_wa[b * 4 + 3] = e3 * inv;
}

// ---------------- att[b,n,d] ----------------------------------------------------
__global__ __launch_bounds__(256) void k_att(const float* __restrict__ hidden)
{
    int idx = blockIdx.x * 256 + threadIdx.x;
    if (idx >= BSZ * NN * DD) return;
    int d = idx & 127;
    int n = (idx >> 7) & 1023;
    int b = idx >> 17;
    int h = d & 63;
    bool isIm = d >= 64;
    float acc = 0.f;
#pragma unroll
    for (int k = 0; k < 4; k++) {
        const float* hb = hidden + ((size_t)(b * 4 + k) << 17);
        float re = hb[(n << 7) + h];
        float im = hb[(n << 7) + 64 + h];
        float c = g_cos[(k << 16) + (n << 6) + h];
        float s = g_sin[(k << 16) + (n << 6) + h];
        float v = isIm ? (s * re + c * im) : (c * re - s * im);
        acc += g_wa[b * 4 + k] * v;
    }
    g_att[idx] = acc;
}

// ---------------- final: out = gco@W + b + att ; also writes new_hidden[:,3] ---
// BM=64 BN=128 (full D), K=128, same tiling as gemm2
__global__ __launch_bounds__(256) void k_final(const float* __restrict__ W,
                                               const float* __restrict__ bias,
                                               float* __restrict__ out)
{
    const int row0 = blockIdx.x * 64;

    __shared__ float As[16][68];
    __shared__ float Bs[16][132];

    const int tid = threadIdx.x;
    const int a_r = tid >> 2;
    const int a_c = (tid & 3) << 2;
    const int b_r = tid >> 5;
    const int b_c = (tid & 31) << 2;
    const int ty  = tid >> 4;
    const int tx  = tid & 15;

    float acc[4][8];
#pragma unroll
    for (int i = 0; i < 4; i++)
#pragma unroll
        for (int j = 0; j < 8; j++) acc[i][j] = 0.f;

    for (int k0 = 0; k0 < 128; k0 += 16) {
        float4 av = *(const float4*)(g_gco + (size_t)(row0 + a_r) * 128 + k0 + a_c);
        float4 b0 = *(const float4*)(W + (size_t)(k0 + b_r) * 128 + b_c);
        float4 b1 = *(const float4*)(W + (size_t)(k0 + b_r + 8) * 128 + b_c);
        __syncthreads();
        As[a_c + 0][a_r] = av.x; As[a_c + 1][a_r] = av.y;
        As[a_c + 2][a_r] = av.z; As[a_c + 3][a_r] = av.w;
        *(float4*)&Bs[b_r][b_c]     = b0;
        *(float4*)&Bs[b_r + 8][b_c] = b1;
        __syncthreads();
#pragma unroll
        for (int kk = 0; kk < 16; kk++) {
            float ar[4], br[8];
            *(float4*)&ar[0] = *(const float4*)&As[kk][ty * 4];
            *(float4*)&br[0] = *(const float4*)&Bs[kk][tx * 8];
            *(float4*)&br[4] = *(const float4*)&Bs[kk][tx * 8 + 4];
#pragma unroll
            for (int i = 0; i < 4; i++)
#pragma unroll
                for (int j = 0; j < 8; j++) acc[i][j] += ar[i] * br[j];
        }
    }

#pragma unroll
    for (int i = 0; i < 4; i++) {
        int rr = row0 + ty * 4 + i;
        int b  = rr >> 10;
        int n  = rr & 1023;
        size_t nh_off = (size_t)OUT0 + (((size_t)(b * 4 + 3) << 10 | n) << 7);
#pragma unroll
        for (int j = 0; j < 8; j++) {
            int col = tx * 8 + j;
            float v = acc[i][j] + bias[(size_t)n * 128 + col] + g_att[(size_t)rr * 128 + col];
            out[(size_t)rr * 128 + col] = v;      // output
            out[nh_off + col]           = v;      // new_hidden[:, 3]
        }
    }
}

// ---------------- new_hidden[:, 0:3] = hidden[:, 1:4] --------------------------
__global__ __launch_bounds__(256) void k_copy(const float* __restrict__ hidden,
                                              float* __restrict__ out)
{
    int i4 = blockIdx.x * 256 + threadIdx.x;         // float4 index
    const int per_b = 3 * (NN * DD) / 4;             // 98304 float4 per batch
    if (i4 >= BSZ * per_b) return;
    int b  = i4 / per_b;
    int r4 = i4 - b * per_b;
    const float4* hv = (const float4*)hidden;
    float4* ov = (float4*)out;
    // src: hidden[b, 1.. ] ; per-batch hidden = 4*N*D floats = 131072 float4
    ov[(OUT0 / 4) + (size_t)b * 131072 + r4] = hv[(size_t)b * 131072 + 32768 + r4];
}

// ---------------- launch ---------------------------------------------------------
extern "C" void kernel_launch(void* const* d_in, const int* in_sizes, int n_in,
                              void* d_out, int out_size)
{
    const float* inputs   = (const float*)d_in[0];
    const float* supports = (const float*)d_in[1];
    const float* hidden   = (const float*)d_in[2];
    const float* W        = (const float*)d_in[3];
    const float* bias     = (const float*)d_in[4];
    const float* R        = (const float*)d_in[5];
    // d_in[6] gc_w, d_in[7] gc_b, d_in[8..9] ev_att (dead), d_in[10..11] att
    const float* gc_w  = (const float*)d_in[6];
    const float* gc_b  = (const float*)d_in[7];
    const float* att_w = (const float*)d_in[10];
    const float* att_b = (const float*)d_in[11];
    float* out = (float*)d_out;

    k_build_x0<<<(XSZ + 255) / 256, 256>>>(inputs, hidden);
    k_wt<<<(1024 * 128 + 255) / 256, 256>>>(gc_w);
    k_cs<<<(PREK * NN * HIDD + 255) / 256, 256>>>(R);

    dim3 gC(CC / 128, NN / 128, BSZ);   // (2, 8, 16)
    k_cheb<<<gC, 256>>>(supports, 0);
    k_cheb<<<gC, 256>>>(supports, 1);
    k_cheb<<<gC, 256>>>(supports, 2);

    k_gemm2<<<(BSZ * NN) / 64, 256>>>(gc_b);

    k_sa<<<dim3(PREK, BSZ), 256>>>(hidden, att_w, att_b);
    k_softmax<<<1, 32>>>();
    k_att<<<(BSZ * NN * DD + 255) / 256, 256>>>(hidden);

    k_final<<<(BSZ * NN) / 64, 256>>>(W, bias, out);
    k_copy<<<(BSZ * 3 * NN * DD / 4 + 255) / 256, 256>>>(hidden, out);
}

// round 3
// speedup vs baseline: 1.9516x; 1.9516x over previous
#include <cuda_runtime.h>
#include <cuda_bf16.h>
#include <cstdint>

#define BSZ   16
#define NN    1024
#define HIDD  64
#define DD    128      // 2*HID
#define CC    256      // F + D
#define PREK  4

#define XSZ   (BSZ * NN * CC)
#define OUT0  (BSZ * NN * DD)

#define PHASE_SCALE ((float)(3.141592653589793 / 0.21875))

// ===================== base-ISA tensor helpers (sm_80+) =====================
__device__ __forceinline__ uint32_t smem_to_u32(const void* p) {
    uint32_t a;
    asm("{ .reg .u64 t; cvta.to.shared.u64 t, %1; cvt.u32.u64 %0, t; }" : "=r"(a) : "l"(p));
    return a;
}
__device__ __forceinline__ void ldmx4(uint32_t* r, uint32_t addr) {
    asm volatile("ldmatrix.sync.aligned.m8n8.x4.shared.b16 {%0,%1,%2,%3}, [%4];"
        : "=r"(r[0]), "=r"(r[1]), "=r"(r[2]), "=r"(r[3]) : "r"(addr));
}
__device__ __forceinline__ void mma16816(float* c, const uint32_t* a, const uint32_t* b) {
    asm volatile("mma.sync.aligned.m16n8k16.row.col.f32.bf16.bf16.f32 "
        "{%0,%1,%2,%3}, {%4,%5,%6,%7}, {%8,%9}, {%0,%1,%2,%3};"
        : "+f"(c[0]), "+f"(c[1]), "+f"(c[2]), "+f"(c[3])
        : "r"(a[0]), "r"(a[1]), "r"(a[2]), "r"(a[3]), "r"(b[0]), "r"(b[1]));
}
#define CP16(dst, src) \
    asm volatile("cp.async.cg.shared.global [%0], [%1], 16;" :: "r"(dst), "l"(src))
#define CP_COMMIT() asm volatile("cp.async.commit_group;" ::: "memory")
#define CP_WAIT1()  asm volatile("cp.async.wait_group 1;" ::: "memory")
#define CP_WAIT0()  asm volatile("cp.async.wait_group 0;" ::: "memory")
#define SWZ(off) ((off) ^ (((off) >> 3) & 0x70))

// ========================= scratch =========================
__device__ __align__(16) __nv_bfloat16 g_shi[BSZ * NN * NN];   // supports hi (m x k)
__device__ __align__(16) __nv_bfloat16 g_slo[BSZ * NN * NN];   // supports lo
__device__ __align__(16) __nv_bfloat16 g_xth[3][BSZ * CC * NN]; // x^T hi [c][n]  (cheb B)
__device__ __align__(16) __nv_bfloat16 g_xtl[3][BSZ * CC * NN]; // x^T lo
__device__ __align__(16) __nv_bfloat16 g_xrh[4][XSZ];          // x row-major hi [n][c]
__device__ __align__(16) __nv_bfloat16 g_xrl[4][XSZ];          // x row-major lo
__device__ __align__(16) __nv_bfloat16 g_wth[4 * 128 * 256];   // gc_w^T hi [m][d][c]
__device__ __align__(16) __nv_bfloat16 g_wtl[4 * 128 * 256];   // gc_w^T lo
__device__ float g_gco[BSZ * NN * DD];
__device__ float g_cos[PREK * NN * HIDD];
__device__ float g_sin[PREK * NN * HIDD];
__device__ float g_att[BSZ * NN * DD];
__device__ float g_sa[BSZ * PREK];
__device__ float g_wa[BSZ * PREK];

// ---------------- S -> bf16 hi/lo --------------------------------------
__global__ __launch_bounds__(256) void k_sconv(const float* __restrict__ S)
{
    int i = blockIdx.x * 256 + threadIdx.x;
    const int total = BSZ * NN * NN / 4;
    if (i >= total) return;
    float4 v = ((const float4*)S)[i];
    __nv_bfloat16 h0 = __float2bfloat16(v.x), h1 = __float2bfloat16(v.y);
    __nv_bfloat16 h2 = __float2bfloat16(v.z), h3 = __float2bfloat16(v.w);
    __nv_bfloat16 l0 = __float2bfloat16(v.x - __bfloat162float(h0));
    __nv_bfloat16 l1 = __float2bfloat16(v.y - __bfloat162float(h1));
    __nv_bfloat16 l2 = __float2bfloat16(v.z - __bfloat162float(h2));
    __nv_bfloat16 l3 = __float2bfloat16(v.w - __bfloat162float(h3));
    __nv_bfloat162* ph = (__nv_bfloat162*)g_shi;
    __nv_bfloat162* pl = (__nv_bfloat162*)g_slo;
    ph[i * 2]     = __nv_bfloat162(h0, h1);
    ph[i * 2 + 1] = __nv_bfloat162(h2, h3);
    pl[i * 2]     = __nv_bfloat162(l0, l1);
    pl[i * 2 + 1] = __nv_bfloat162(l2, l3);
}

// ---------------- build x0: row-major hi/lo + transposed hi/lo ----------
__global__ __launch_bounds__(256) void k_build_x0(const float* __restrict__ inputs,
                                                  const float* __restrict__ hidden)
{
    __shared__ float tile[32][33];
    const int n0 = blockIdx.x * 32;
    const int c0 = blockIdx.y * 32;
    const int b  = blockIdx.z;
    const int lane = threadIdx.x & 31;
    const int wrp  = threadIdx.x >> 5;

#pragma unroll
    for (int r = 0; r < 4; r++) {
        int nl = wrp * 4 + r;
        int n = n0 + nl;
        int c = c0 + lane;
        float v;
        if (c < 64)        v = inputs[((size_t)(b * NN + n)) * 128 + c];
        else if (c < 128)  v = hidden[(((size_t)(b * 4 + 3) * NN + n)) * 128 + (c - 64)];
        else if (c < 192)  v = inputs[((size_t)(b * NN + n)) * 128 + (c - 128 + 64)];
        else               v = hidden[(((size_t)(b * 4 + 3) * NN + n)) * 128 + (c - 192 + 64)];
        __nv_bfloat16 h = __float2bfloat16(v);
        __nv_bfloat16 l = __float2bfloat16(v - __bfloat162float(h));
        size_t o = ((size_t)(b * NN + n)) * CC + c;
        g_xrh[0][o] = h;
        g_xrl[0][o] = l;
        tile[nl][lane] = v;
    }
    __syncthreads();
#pragma unroll
    for (int r = 0; r < 4; r++) {
        int cl = wrp * 4 + r;
        float v = tile[lane][cl];
        __nv_bfloat16 h = __float2bfloat16(v);
        __nv_bfloat16 l = __float2bfloat16(v - __bfloat162float(h));
        size_t o = ((size_t)b * CC + c0 + cl) * NN + n0 + lane;
        g_xth[0][o] = h;
        g_xtl[0][o] = l;
    }
}

// ---------------- gc_w -> wtT hi/lo [m][d][c] ---------------------------
__global__ __launch_bounds__(256) void k_wt(const float* __restrict__ gc_w)
{
    int i = blockIdx.x * 256 + threadIdx.x;   // over 4*128*256
    if (i >= 4 * 128 * 256) return;
    int c = i & 255;
    int d = (i >> 8) & 127;
    int m = i >> 15;
    float v = gc_w[(size_t)d * 1024 + c * 4 + m];
    __nv_bfloat16 h = __float2bfloat16(v);
    g_wth[i] = h;
    g_wtl[i] = __float2bfloat16(v - __bfloat162float(h));
}

// ---------------- cos/sin tables ----------------------------------------
__global__ __launch_bounds__(256) void k_cs(const float* __restrict__ R)
{
    int i = blockIdx.x * 256 + threadIdx.x;
    if (i >= PREK * NN * HIDD) return;
    float ph = R[i] * PHASE_SCALE;
    float s, c;
    sincosf(ph, &s, &c);
    g_cos[i] = c;
    g_sin[i] = s;
}

// =================== HMMA Chebyshev GEMM =================================
// grid (2 ct, 8 mt, 16 b). CTA tile 128x128, BK=64, double-buffered cp.async.
// smem stage: Ahi 16K | Alo 16K | Bhi 16K | Blo 16K = 64K; x2 = 128K.
#define CH_STAGE 65536
#define CH_SMEM  (2 * CH_STAGE)

__device__ __forceinline__ void cheb_load_stage(uint32_t sb, int buf, int tid,
    const __nv_bfloat16* A_h, const __nv_bfloat16* A_l,
    const __nv_bfloat16* B_h, const __nv_bfloat16* B_l, int k0)
{
    const uint32_t st = sb + buf * CH_STAGE;
#pragma unroll
    for (int i = 0; i < 4; i++) {
        int idx = tid + i * 256;          // 0..1023
        int row = idx >> 3;
        int c16 = idx & 7;
        uint32_t off = SWZ((uint32_t)(row * 128 + c16 * 16));
        size_t src = (size_t)row * 1024 + k0 + c16 * 8;
        CP16(st + off,         A_h + src);
        CP16(st + 16384 + off, A_l + src);
        CP16(st + 32768 + off, B_h + src);
        CP16(st + 49152 + off, B_l + src);
    }
    CP_COMMIT();
}

__device__ __forceinline__ void hmma_compute_stage(uint32_t st, int warpM, int warpN,
                                                   int lane, float acc[2][8][4])
{
    const int arow = lane & 15;
    const int acol = (lane >> 4) << 4;
    const int g    = lane >> 3;
    const int brow = ((g >> 1) << 3) + (lane & 7);
    const int bcol = (g & 1) << 4;
#pragma unroll
    for (int ks = 0; ks < 4; ks++) {
        uint32_t ah[2][4], al[2][4], bh[4][4], bl[4][4];
#pragma unroll
        for (int mt = 0; mt < 2; mt++) {
            uint32_t off = SWZ((uint32_t)((warpM + mt * 16 + arow) * 128 + ks * 32 + acol));
            ldmx4(ah[mt], st + off);
            ldmx4(al[mt], st + 16384 + off);
        }
#pragma unroll
        for (int np = 0; np < 4; np++) {
            uint32_t off = SWZ((uint32_t)((warpN + np * 16 + brow) * 128 + ks * 32 + bcol));
            ldmx4(bh[np], st + 32768 + off);
            ldmx4(bl[np], st + 49152 + off);
        }
#pragma unroll
        for (int mt = 0; mt < 2; mt++)
#pragma unroll
            for (int np = 0; np < 4; np++) {
                mma16816(acc[mt][np * 2],     ah[mt], &bh[np][0]);
                mma16816(acc[mt][np * 2],     ah[mt], &bl[np][0]);
                mma16816(acc[mt][np * 2],     al[mt], &bh[np][0]);
                mma16816(acc[mt][np * 2 + 1], ah[mt], &bh[np][2]);
                mma16816(acc[mt][np * 2 + 1], ah[mt], &bl[np][2]);
                mma16816(acc[mt][np * 2 + 1], al[mt], &bh[np][2]);
            }
    }
}

__global__ __launch_bounds__(256, 1) void k_cheb_mma(int hop)
{
    extern __shared__ char smem[];
    const uint32_t sb = smem_to_u32(smem);
    const int tid = threadIdx.x;
    const int wid = tid >> 5;
    const int lane = tid & 31;
    const int ct0 = blockIdx.x * 128;
    const int row0 = blockIdx.y * 128;
    const int b = blockIdx.z;
    const int warpM = (wid & 3) * 32;
    const int warpN = (wid >> 2) * 64;

    const __nv_bfloat16* A_h = g_shi + ((size_t)b * NN + row0) * NN;
    const __nv_bfloat16* A_l = g_slo + ((size_t)b * NN + row0) * NN;
    const __nv_bfloat16* B_h = g_xth[hop] + ((size_t)b * CC + ct0) * NN;
    const __nv_bfloat16* B_l = g_xtl[hop] + ((size_t)b * CC + ct0) * NN;

    float acc[2][8][4];
#pragma unroll
    for (int i = 0; i < 2; i++)
#pragma unroll
        for (int j = 0; j < 8; j++)
#pragma unroll
            for (int q = 0; q < 4; q++) acc[i][j][q] = 0.f;

    cheb_load_stage(sb, 0, tid, A_h, A_l, B_h, B_l, 0);

    for (int s = 0; s < 16; s++) {
        if (s + 1 < 16) {
            cheb_load_stage(sb, (s + 1) & 1, tid, A_h, A_l, B_h, B_l, (s + 1) * 64);
            CP_WAIT1();
        } else {
            CP_WAIT0();
        }
        __syncthreads();
        hmma_compute_stage(sb + (s & 1) * CH_STAGE, warpM, warpN, lane, acc);
        __syncthreads();
    }

    // ---------------- epilogue ----------------
    const int qr = lane >> 2;
    const int qc = (lane & 3) * 2;
    const size_t rmBase = (size_t)b * NN * CC;
    const __nv_bfloat16* pH = (hop >= 1) ? g_xrh[hop - 1] : nullptr;
    const __nv_bfloat16* pL = (hop >= 1) ? g_xrl[hop - 1] : nullptr;
    __nv_bfloat16* oH = g_xrh[hop + 1];
    __nv_bfloat16* oL = g_xrl[hop + 1];
    __nv_bfloat16* tH = (hop < 2) ? g_xth[hop + 1] : nullptr;
    __nv_bfloat16* tL = (hop < 2) ? g_xtl[hop + 1] : nullptr;

#pragma unroll
    for (int mt = 0; mt < 2; mt++)
#pragma unroll
        for (int half = 0; half < 2; half++) {
            int row = row0 + warpM + mt * 16 + half * 8 + qr;
#pragma unroll
            for (int nt = 0; nt < 8; nt++) {
                int col = ct0 + warpN + nt * 8 + qc;
                float v0 = acc[mt][nt][half * 2 + 0];
                float v1 = acc[mt][nt][half * 2 + 1];
                size_t idx = rmBase + (size_t)row * CC + col;
                if (hop >= 1) {
                    __nv_bfloat162 phv = *(const __nv_bfloat162*)(pH + idx);
                    __nv_bfloat162 plv = *(const __nv_bfloat162*)(pL + idx);
                    v0 = 2.f * v0 - (__bfloat162float(phv.x) + __bfloat162float(plv.x));
                    v1 = 2.f * v1 - (__bfloat162float(phv.y) + __bfloat162float(plv.y));
                }
                __nv_bfloat16 h0 = __float2bfloat16(v0);
                __nv_bfloat16 l0 = __float2bfloat16(v0 - __bfloat162float(h0));
                __nv_bfloat16 h1 = __float2bfloat16(v1);
                __nv_bfloat16 l1 = __float2bfloat16(v1 - __bfloat162float(h1));
                *(__nv_bfloat162*)(oH + idx) = __nv_bfloat162(h0, h1);
                *(__nv_bfloat162*)(oL + idx) = __nv_bfloat162(l0, l1);
                if (hop < 2) {
                    size_t t0 = (size_t)b * CC * NN + (size_t)col * NN + row;
                    tH[t0] = h0;       tL[t0] = l0;
                    tH[t0 + NN] = h1;  tL[t0 + NN] = l1;
                }
            }
        }
}

// =================== HMMA gemm2: gco = sum_m x_m @ wtT_m^T ===============
// grid 128 CTAs (m tiles). CTA 128x128, 16 stages = 4 hops x 4 k-chunks.
__global__ __launch_bounds__(256, 1) void k_gemm2_mma(const float* __restrict__ gc_b)
{
    extern __shared__ char smem[];
    const uint32_t sb = smem_to_u32(smem);
    const int tid = threadIdx.x;
    const int wid = tid >> 5;
    const int lane = tid & 31;
    const int row0 = blockIdx.x * 128;
    const int warpM = (wid & 3) * 32;
    const int warpN = (wid >> 2) * 64;

    float acc[2][8][4];
#pragma unroll
    for (int i = 0; i < 2; i++)
#pragma unroll
        for (int j = 0; j < 8; j++)
#pragma unroll
            for (int q = 0; q < 4; q++) acc[i][j][q] = 0.f;

    // stage loader (A row stride 256, B row stride 256)
    auto load = [&](int s, int buf) {
        const int m  = s >> 2;
        const int c0 = (s & 3) * 64;
        const __nv_bfloat16* A_h = g_xrh[m] + (size_t)row0 * 256;
        const __nv_bfloat16* A_l = g_xrl[m] + (size_t)row0 * 256;
        const __nv_bfloat16* B_h = g_wth + m * 32768;
        const __nv_bfloat16* B_l = g_wtl + m * 32768;
        const uint32_t st = sb + buf * CH_STAGE;
#pragma unroll
        for (int i = 0; i < 4; i++) {
            int idx = tid + i * 256;
            int row = idx >> 3;
            int c16 = idx & 7;
            uint32_t off = SWZ((uint32_t)(row * 128 + c16 * 16));
            size_t src = (size_t)row * 256 + c0 + c16 * 8;
            CP16(st + off,         A_h + src);
            CP16(st + 16384 + off, A_l + src);
            CP16(st + 32768 + off, B_h + src);
            CP16(st + 49152 + off, B_l + src);
        }
        CP_COMMIT();
    };

    load(0, 0);
    for (int s = 0; s < 16; s++) {
        if (s + 1 < 16) { load(s + 1, (s + 1) & 1); CP_WAIT1(); }
        else           { CP_WAIT0(); }
        __syncthreads();
        hmma_compute_stage(sb + (s & 1) * CH_STAGE, warpM, warpN, lane, acc);
        __syncthreads();
    }

    const int qr = lane >> 2;
    const int qc = (lane & 3) * 2;
#pragma unroll
    for (int mt = 0; mt < 2; mt++)
#pragma unroll
        for (int half = 0; half < 2; half++) {
            int row = row0 + warpM + mt * 16 + half * 8 + qr;
#pragma unroll
            for (int nt = 0; nt < 8; nt++) {
                int col = warpN + nt * 8 + qc;
                float v0 = acc[mt][nt][half * 2 + 0] + gc_b[col];
                float v1 = acc[mt][nt][half * 2 + 1] + gc_b[col + 1];
                v0 = (v0 >= 0.f) ? v0 : 0.01f * v0;
                v1 = (v1 >= 0.f) ? v1 : 0.01f * v1;
                *(float2*)(g_gco + (size_t)row * 128 + col) = make_float2(v0, v1);
            }
        }
}

// ---------------- sa[b,k] reduction ---------------------------------------
__global__ __launch_bounds__(256) void k_sa(const float* __restrict__ hidden,
                                            const float* __restrict__ att_w,
                                            const float* __restrict__ att_b)
{
    const int k = blockIdx.x;
    const int b = blockIdx.y;
    const float* hb = hidden + ((size_t)(b * 4 + k) << 17);
    const int tid = threadIdx.x;

    float sum = 0.f;
    for (int i = tid; i < NN * HIDD; i += 256) {
        int n = i >> 6, h = i & 63;
        float re = hb[(n << 7) + h];
        float im = hb[(n << 7) + 64 + h];
        float c = g_cos[(k << 16) + i];
        float s = g_sin[(k << 16) + i];
        sum += (c * re - s * im) * att_w[(n << 7) + h]
             + (s * re + c * im) * att_w[(n << 7) + 64 + h];
    }
    __shared__ float red[8];
    for (int o = 16; o; o >>= 1) sum += __shfl_down_sync(0xffffffffu, sum, o);
    if ((tid & 31) == 0) red[tid >> 5] = sum;
    __syncthreads();
    if (tid < 8) {
        float v = red[tid];
        for (int o = 4; o; o >>= 1) v += __shfl_down_sync(0xffu, v, o);
        if (tid == 0) g_sa[b * 4 + k] = v + att_b[0];
    }
}

__global__ void k_softmax()
{
    int b = threadIdx.x;
    if (b >= BSZ) return;
    float s0 = g_sa[b * 4 + 0], s1 = g_sa[b * 4 + 1];
    float s2 = g_sa[b * 4 + 2], s3 = g_sa[b * 4 + 3];
    float m = fmaxf(fmaxf(s0, s1), fmaxf(s2, s3));
    float e0 = expf(s0 - m), e1 = expf(s1 - m), e2 = expf(s2 - m), e3 = expf(s3 - m);
    float inv = 1.f / (e0 + e1 + e2 + e3);
    g_wa[b * 4 + 0] = e0 * inv;
    g_wa[b * 4 + 1] = e1 * inv;
    g_wa[b * 4 + 2] = e2 * inv;
    g_wa[b * 4 + 3] = e3 * inv;
}

__global__ __launch_bounds__(256) void k_att(const float* __restrict__ hidden)
{
    int idx = blockIdx.x * 256 + threadIdx.x;
    if (idx >= BSZ * NN * DD) return;
    int d = idx & 127;
    int n = (idx >> 7) & 1023;
    int b = idx >> 17;
    int h = d & 63;
    bool isIm = d >= 64;
    float acc = 0.f;
#pragma unroll
    for (int k = 0; k < 4; k++) {
        const float* hb = hidden + ((size_t)(b * 4 + k) << 17);
        float re = hb[(n << 7) + h];
        float im = hb[(n << 7) + 64 + h];
        float c = g_cos[(k << 16) + (n << 6) + h];
        float s = g_sin[(k << 16) + (n << 6) + h];
        float v = isIm ? (s * re + c * im) : (c * re - s * im);
        acc += g_wa[b * 4 + k] * v;
    }
    g_att[idx] = acc;
}

// ---------------- final: out = gco@W + b + att (fp32 SGEMM) ---------------
__global__ __launch_bounds__(256) void k_final(const float* __restrict__ W,
                                               const float* __restrict__ bias,
                                               float* __restrict__ out)
{
    const int row0 = blockIdx.x * 64;
    __shared__ float As[16][68];
    __shared__ float Bs[16][132];
    const int tid = threadIdx.x;
    const int a_r = tid >> 2;
    const int a_c = (tid & 3) << 2;
    const int b_r = tid >> 5;
    const int b_c = (tid & 31) << 2;
    const int ty  = tid >> 4;
    const int tx  = tid & 15;

    float acc[4][8];
#pragma unroll
    for (int i = 0; i < 4; i++)
#pragma unroll
        for (int j = 0; j < 8; j++) acc[i][j] = 0.f;

    for (int k0 = 0; k0 < 128; k0 += 16) {
        float4 av = *(const float4*)(g_gco + (size_t)(row0 + a_r) * 128 + k0 + a_c);
        float4 b0 = *(const float4*)(W + (size_t)(k0 + b_r) * 128 + b_c);
        float4 b1 = *(const float4*)(W + (size_t)(k0 + b_r + 8) * 128 + b_c);
        __syncthreads();
        As[a_c + 0][a_r] = av.x; As[a_c + 1][a_r] = av.y;
        As[a_c + 2][a_r] = av.z; As[a_c + 3][a_r] = av.w;
        *(float4*)&Bs[b_r][b_c]     = b0;
        *(float4*)&Bs[b_r + 8][b_c] = b1;
        __syncthreads();
#pragma unroll
        for (int kk = 0; kk < 16; kk++) {
            float ar[4], br[8];
            *(float4*)&ar[0] = *(const float4*)&As[kk][ty * 4];
            *(float4*)&br[0] = *(const float4*)&Bs[kk][tx * 8];
            *(float4*)&br[4] = *(const float4*)&Bs[kk][tx * 8 + 4];
#pragma unroll
            for (int i = 0; i < 4; i++)
#pragma unroll
                for (int j = 0; j < 8; j++) acc[i][j] += ar[i] * br[j];
        }
    }
#pragma unroll
    for (int i = 0; i < 4; i++) {
        int rr = row0 + ty * 4 + i;
        int b  = rr >> 10;
        int n  = rr & 1023;
        size_t nh_off = (size_t)OUT0 + (((size_t)(b * 4 + 3) << 10 | n) << 7);
#pragma unroll
        for (int j = 0; j < 8; j++) {
            int col = tx * 8 + j;
            float v = acc[i][j] + bias[(size_t)n * 128 + col] + g_att[(size_t)rr * 128 + col];
            out[(size_t)rr * 128 + col] = v;
            out[nh_off + col]           = v;
        }
    }
}

__global__ __launch_bounds__(256) void k_copy(const float* __restrict__ hidden,
                                              float* __restrict__ out)
{
    int i4 = blockIdx.x * 256 + threadIdx.x;
    const int per_b = 3 * (NN * DD) / 4;
    if (i4 >= BSZ * per_b) return;
    int b  = i4 / per_b;
    int r4 = i4 - b * per_b;
    const float4* hv = (const float4*)hidden;
    float4* ov = (float4*)out;
    ov[(OUT0 / 4) + (size_t)b * 131072 + r4] = hv[(size_t)b * 131072 + 32768 + r4];
}

// ---------------- launch ---------------------------------------------------
extern "C" void kernel_launch(void* const* d_in, const int* in_sizes, int n_in,
                              void* d_out, int out_size)
{
    const float* inputs   = (const float*)d_in[0];
    const float* supports = (const float*)d_in[1];
    const float* hidden   = (const float*)d_in[2];
    const float* W        = (const float*)d_in[3];
    const float* bias     = (const float*)d_in[4];
    const float* R        = (const float*)d_in[5];
    const float* gc_w  = (const float*)d_in[6];
    const float* gc_b  = (const float*)d_in[7];
    const float* att_w = (const float*)d_in[10];
    const float* att_b = (const float*)d_in[11];
    float* out = (float*)d_out;

    static bool attrs_set = false;
    if (!attrs_set) {
        cudaFuncSetAttribute(k_cheb_mma, cudaFuncAttributeMaxDynamicSharedMemorySize, CH_SMEM);
        cudaFuncSetAttribute(k_gemm2_mma, cudaFuncAttributeMaxDynamicSharedMemorySize, CH_SMEM);
        attrs_set = true;
    }

    k_sconv<<<(BSZ * NN * NN / 4 + 255) / 256, 256>>>(supports);
    k_build_x0<<<dim3(NN / 32, CC / 32, BSZ), 256>>>(inputs, hidden);
    k_wt<<<(4 * 128 * 256 + 255) / 256, 256>>>(gc_w);
    k_cs<<<(PREK * NN * HIDD + 255) / 256, 256>>>(R);

    dim3 gC(2, 8, BSZ);
    k_cheb_mma<<<gC, 256, CH_SMEM>>>(0);
    k_cheb_mma<<<gC, 256, CH_SMEM>>>(1);
    k_cheb_mma<<<gC, 256, CH_SMEM>>>(2);

    k_gemm2_mma<<<128, 256, CH_SMEM>>>(gc_b);

    k_sa<<<dim3(PREK, BSZ), 256>>>(hidden, att_w, att_b);
    k_softmax<<<1, 32>>>();
    k_att<<<(BSZ * NN * DD + 255) / 256, 256>>>(hidden);

    k_final<<<(BSZ * NN) / 64, 256>>>(W, bias, out);
    k_copy<<<(BSZ * 3 * NN * DD / 4 + 255) / 256, 256>>>(hidden, out);
}

// round 4
// speedup vs baseline: 1.9802x; 1.0147x over previous
#include <cuda_runtime.h>
#include <cuda_bf16.h>
#include <cstdint>

#define BSZ   16
#define NN    1024
#define HIDD  64
#define DD    128
#define CC    256
#define PREK  4

#define XSZ   (BSZ * NN * CC)
#define OUT0  (BSZ * NN * DD)

#define PHASE_SCALE ((float)(3.141592653589793 / 0.21875))

// ===================== base-ISA tensor helpers (sm_80+) =====================
__device__ __forceinline__ uint32_t smem_to_u32(const void* p) {
    uint32_t a;
    asm("{ .reg .u64 t; cvta.to.shared.u64 t, %1; cvt.u32.u64 %0, t; }" : "=r"(a) : "l"(p));
    return a;
}
__device__ __forceinline__ void ldmx4(uint32_t* r, uint32_t addr) {
    asm volatile("ldmatrix.sync.aligned.m8n8.x4.shared.b16 {%0,%1,%2,%3}, [%4];"
        : "=r"(r[0]), "=r"(r[1]), "=r"(r[2]), "=r"(r[3]) : "r"(addr));
}
__device__ __forceinline__ void mma16816(float* c, const uint32_t* a, const uint32_t* b) {
    asm volatile("mma.sync.aligned.m16n8k16.row.col.f32.bf16.bf16.f32 "
        "{%0,%1,%2,%3}, {%4,%5,%6,%7}, {%8,%9}, {%0,%1,%2,%3};"
        : "+f"(c[0]), "+f"(c[1]), "+f"(c[2]), "+f"(c[3])
        : "r"(a[0]), "r"(a[1]), "r"(a[2]), "r"(a[3]), "r"(b[0]), "r"(b[1]));
}
#define CP16(dst, src) \
    asm volatile("cp.async.cg.shared.global [%0], [%1], 16;" :: "r"(dst), "l"(src))
#define CP_COMMIT() asm volatile("cp.async.commit_group;" ::: "memory")
#define CP_WAIT1()  asm volatile("cp.async.wait_group 1;" ::: "memory")
#define CP_WAIT0()  asm volatile("cp.async.wait_group 0;" ::: "memory")
#define SWZ(off) ((off) ^ (((off) >> 3) & 0x70))

// ========================= scratch =========================
__device__ __align__(16) __nv_bfloat16 g_shi[BSZ * NN * NN];
__device__ __align__(16) __nv_bfloat16 g_slo[BSZ * NN * NN];
__device__ __align__(16) __nv_bfloat16 g_xth[3][BSZ * CC * NN];
__device__ __align__(16) __nv_bfloat16 g_xtl[3][BSZ * CC * NN];
__device__ __align__(16) __nv_bfloat16 g_xrh[4][XSZ];
__device__ __align__(16) __nv_bfloat16 g_xrl[4][XSZ];
__device__ __align__(16) __nv_bfloat16 g_wth[4 * 128 * 256];
__device__ __align__(16) __nv_bfloat16 g_wtl[4 * 128 * 256];
__device__ float g_gco[BSZ * NN * DD];
__device__ float g_cos[PREK * NN * HIDD];
__device__ float g_sin[PREK * NN * HIDD];
__device__ float g_att[BSZ * NN * DD];
__device__ float g_sa[BSZ * PREK];
__device__ float g_wa[BSZ * PREK];

// ---------------- S -> bf16 hi/lo --------------------------------------
__global__ __launch_bounds__(256) void k_sconv(const float* __restrict__ S)
{
    int i = blockIdx.x * 256 + threadIdx.x;
    const int total = BSZ * NN * NN / 4;
    if (i >= total) return;
    float4 v = ((const float4*)S)[i];
    __nv_bfloat16 h0 = __float2bfloat16(v.x), h1 = __float2bfloat16(v.y);
    __nv_bfloat16 h2 = __float2bfloat16(v.z), h3 = __float2bfloat16(v.w);
    __nv_bfloat16 l0 = __float2bfloat16(v.x - __bfloat162float(h0));
    __nv_bfloat16 l1 = __float2bfloat16(v.y - __bfloat162float(h1));
    __nv_bfloat16 l2 = __float2bfloat16(v.z - __bfloat162float(h2));
    __nv_bfloat16 l3 = __float2bfloat16(v.w - __bfloat162float(h3));
    __nv_bfloat162* ph = (__nv_bfloat162*)g_shi;
    __nv_bfloat162* pl = (__nv_bfloat162*)g_slo;
    ph[i * 2]     = __nv_bfloat162(h0, h1);
    ph[i * 2 + 1] = __nv_bfloat162(h2, h3);
    pl[i * 2]     = __nv_bfloat162(l0, l1);
    pl[i * 2 + 1] = __nv_bfloat162(l2, l3);
}

// ---------------- build x0: row-major hi/lo + transposed hi/lo ----------
__global__ __launch_bounds__(256) void k_build_x0(const float* __restrict__ inputs,
                                                  const float* __restrict__ hidden)
{
    __shared__ float tile[32][33];
    const int n0 = blockIdx.x * 32;
    const int c0 = blockIdx.y * 32;
    const int b  = blockIdx.z;
    const int lane = threadIdx.x & 31;
    const int wrp  = threadIdx.x >> 5;

#pragma unroll
    for (int r = 0; r < 4; r++) {
        int nl = wrp * 4 + r;
        int n = n0 + nl;
        int c = c0 + lane;
        float v;
        if (c < 64)        v = inputs[((size_t)(b * NN + n)) * 128 + c];
        else if (c < 128)  v = hidden[(((size_t)(b * 4 + 3) * NN + n)) * 128 + (c - 64)];
        else if (c < 192)  v = inputs[((size_t)(b * NN + n)) * 128 + (c - 128 + 64)];
        else               v = hidden[(((size_t)(b * 4 + 3) * NN + n)) * 128 + (c - 192 + 64)];
        __nv_bfloat16 h = __float2bfloat16(v);
        __nv_bfloat16 l = __float2bfloat16(v - __bfloat162float(h));
        size_t o = ((size_t)(b * NN + n)) * CC + c;
        g_xrh[0][o] = h;
        g_xrl[0][o] = l;
        tile[nl][lane] = v;
    }
    __syncthreads();
#pragma unroll
    for (int r = 0; r < 4; r++) {
        int cl = wrp * 4 + r;
        float v = tile[lane][cl];
        __nv_bfloat16 h = __float2bfloat16(v);
        __nv_bfloat16 l = __float2bfloat16(v - __bfloat162float(h));
        size_t o = ((size_t)b * CC + c0 + cl) * NN + n0 + lane;
        g_xth[0][o] = h;
        g_xtl[0][o] = l;
    }
}

// ---------------- gc_w -> wtT hi/lo [m][d][c] ---------------------------
__global__ __launch_bounds__(256) void k_wt(const float* __restrict__ gc_w)
{
    int i = blockIdx.x * 256 + threadIdx.x;
    if (i >= 4 * 128 * 256) return;
    int c = i & 255;
    int d = (i >> 8) & 127;
    int m = i >> 15;
    float v = gc_w[(size_t)d * 1024 + c * 4 + m];
    __nv_bfloat16 h = __float2bfloat16(v);
    g_wth[i] = h;
    g_wtl[i] = __float2bfloat16(v - __bfloat162float(h));
}

// ---------------- cos/sin tables ----------------------------------------
__global__ __launch_bounds__(256) void k_cs(const float* __restrict__ R)
{
    int i = blockIdx.x * 256 + threadIdx.x;
    if (i >= PREK * NN * HIDD) return;
    float ph = R[i] * PHASE_SCALE;
    float s, c;
    sincosf(ph, &s, &c);
    g_cos[i] = c;
    g_sin[i] = s;
}

// =================== shared HMMA stage compute ===========================
// MT = # of 16-row m-tiles per warp. B covered as 4 n16-groups (64 cols).
template<int MT>
__device__ __forceinline__ void hmma_stage(uint32_t st, uint32_t aLoOff,
                                           uint32_t bHiOff, uint32_t bLoOff,
                                           int warpM, int warpN, int lane,
                                           float (*acc)[8][4])
{
    const int arow = lane & 15;
    const int acol = (lane >> 4) << 4;
    const int g    = lane >> 3;
    const int brow = ((g >> 1) << 3) + (lane & 7);
    const int bcol = (g & 1) << 4;
#pragma unroll
    for (int ks = 0; ks < 4; ks++) {
        uint32_t ah[MT][4], al[MT][4], bh[4][4], bl[4][4];
#pragma unroll
        for (int mt = 0; mt < MT; mt++) {
            uint32_t off = SWZ((uint32_t)((warpM + mt * 16 + arow) * 128 + ks * 32 + acol));
            ldmx4(ah[mt], st + off);
            ldmx4(al[mt], st + aLoOff + off);
        }
#pragma unroll
        for (int np = 0; np < 4; np++) {
            uint32_t off = SWZ((uint32_t)((warpN + np * 16 + brow) * 128 + ks * 32 + bcol));
            ldmx4(bh[np], st + bHiOff + off);
            ldmx4(bl[np], st + bLoOff + off);
        }
#pragma unroll
        for (int mt = 0; mt < MT; mt++)
#pragma unroll
            for (int np = 0; np < 4; np++) {
                mma16816(acc[mt][np * 2],     ah[mt], &bh[np][0]);
                mma16816(acc[mt][np * 2],     ah[mt], &bl[np][0]);
                mma16816(acc[mt][np * 2],     al[mt], &bh[np][0]);
                mma16816(acc[mt][np * 2 + 1], ah[mt], &bh[np][2]);
                mma16816(acc[mt][np * 2 + 1], ah[mt], &bl[np][2]);
                mma16816(acc[mt][np * 2 + 1], al[mt], &bh[np][2]);
            }
    }
}

// =================== HMMA Chebyshev GEMM v2 ==============================
// grid (8 mt, 16 b) = 128 CTAs (1 wave). CTA tile 128x256 (full C), BK=64.
// stage 96KB: Ahi 16K | Alo 16K | Bhi 32K | Blo 32K.  2 stages = 192KB.
#define CB_STAGE 98304
#define CB_SMEM  (2 * CB_STAGE)

__device__ __forceinline__ void cheb_load(uint32_t sb, int buf, int tid,
    const __nv_bfloat16* A_h, const __nv_bfloat16* A_l,
    const __nv_bfloat16* B_h, const __nv_bfloat16* B_l, int k0)
{
    const uint32_t st = sb + buf * CB_STAGE;
#pragma unroll
    for (int i = 0; i < 4; i++) {                    // A: 128 rows
        int idx = tid + i * 256;
        int row = idx >> 3;
        int c16 = idx & 7;
        uint32_t off = SWZ((uint32_t)(row * 128 + c16 * 16));
        size_t src = (size_t)row * 1024 + k0 + c16 * 8;
        CP16(st + off,         A_h + src);
        CP16(st + 16384 + off, A_l + src);
    }
#pragma unroll
    for (int i = 0; i < 8; i++) {                    // B: 256 rows
        int idx = tid + i * 256;
        int row = idx >> 3;
        int c16 = idx & 7;
        uint32_t off = SWZ((uint32_t)(row * 128 + c16 * 16));
        size_t src = (size_t)row * 1024 + k0 + c16 * 8;
        CP16(st + 32768 + off, B_h + src);
        CP16(st + 65536 + off, B_l + src);
    }
    CP_COMMIT();
}

__global__ __launch_bounds__(256, 1) void k_cheb_mma(int hop)
{
    extern __shared__ char smem[];
    const uint32_t sb = smem_to_u32(smem);
    const int tid = threadIdx.x;
    const int wid = tid >> 5;
    const int lane = tid & 31;
    const int row0 = blockIdx.x * 128;
    const int b = blockIdx.y;
    const int warpM = (wid & 1) * 64;      // 2 M groups of 64
    const int warpN = (wid >> 1) * 64;     // 4 N groups of 64

    const __nv_bfloat16* A_h = g_shi + ((size_t)b * NN + row0) * NN;
    const __nv_bfloat16* A_l = g_slo + ((size_t)b * NN + row0) * NN;
    const __nv_bfloat16* B_h = g_xth[hop] + (size_t)b * CC * NN;
    const __nv_bfloat16* B_l = g_xtl[hop] + (size_t)b * CC * NN;

    float acc[4][8][4];
#pragma unroll
    for (int i = 0; i < 4; i++)
#pragma unroll
        for (int j = 0; j < 8; j++)
#pragma unroll
            for (int q = 0; q < 4; q++) acc[i][j][q] = 0.f;

    cheb_load(sb, 0, tid, A_h, A_l, B_h, B_l, 0);

    for (int s = 0; s < 16; s++) {
        if (s + 1 < 16) {
            cheb_load(sb, (s + 1) & 1, tid, A_h, A_l, B_h, B_l, (s + 1) * 64);
            CP_WAIT1();
        } else {
            CP_WAIT0();
        }
        __syncthreads();
        hmma_stage<4>(sb + (s & 1) * CB_STAGE, 16384, 32768, 65536,
                      warpM, warpN, lane, acc);
        __syncthreads();
    }

    // ---------------- epilogue ----------------
    const int qr = lane >> 2;
    const int qc = (lane & 3) * 2;
    const size_t rmBase = (size_t)b * NN * CC;
    const __nv_bfloat16* pH = (hop >= 1) ? g_xrh[hop - 1] : nullptr;
    const __nv_bfloat16* pL = (hop >= 1) ? g_xrl[hop - 1] : nullptr;
    __nv_bfloat16* oH = g_xrh[hop + 1];
    __nv_bfloat16* oL = g_xrl[hop + 1];

    uint32_t* T = (uint32_t*)smem;       // [256][129] packed (hi,lo)

#pragma unroll
    for (int mt = 0; mt < 4; mt++)
#pragma unroll
        for (int half = 0; half < 2; half++) {
            int rloc = warpM + mt * 16 + half * 8 + qr;        // 0..127
            int row = row0 + rloc;
#pragma unroll
            for (int nt = 0; nt < 8; nt++) {
                int col = warpN + nt * 8 + qc;                  // 0..255
                float v0 = acc[mt][nt][half * 2 + 0];
                float v1 = acc[mt][nt][half * 2 + 1];
                size_t idx = rmBase + (size_t)row * CC + col;
                if (hop >= 1) {
                    __nv_bfloat162 phv = *(const __nv_bfloat162*)(pH + idx);
                    __nv_bfloat162 plv = *(const __nv_bfloat162*)(pL + idx);
                    v0 = 2.f * v0 - (__bfloat162float(phv.x) + __bfloat162float(plv.x));
                    v1 = 2.f * v1 - (__bfloat162float(phv.y) + __bfloat162float(plv.y));
                }
                __nv_bfloat16 h0 = __float2bfloat16(v0);
                __nv_bfloat16 l0 = __float2bfloat16(v0 - __bfloat162float(h0));
                __nv_bfloat16 h1 = __float2bfloat16(v1);
                __nv_bfloat16 l1 = __float2bfloat16(v1 - __bfloat162float(h1));
                *(__nv_bfloat162*)(oH + idx) = __nv_bfloat162(h0, h1);
                *(__nv_bfloat162*)(oL + idx) = __nv_bfloat162(l0, l1);
                if (hop < 2) {
                    T[(uint32_t)col * 129 + rloc] =
                        (uint32_t)__bfloat16_as_ushort(h0) |
                        ((uint32_t)__bfloat16_as_ushort(l0) << 16);
                    T[(uint32_t)(col + 1) * 129 + rloc] =
                        (uint32_t)__bfloat16_as_ushort(h1) |
                        ((uint32_t)__bfloat16_as_ushort(l1) << 16);
                }
            }
        }

    if (hop < 2) {
        __syncthreads();
        __nv_bfloat16* tH = g_xth[hop + 1] + (size_t)b * CC * NN;
        __nv_bfloat16* tL = g_xtl[hop + 1] + (size_t)b * CC * NN;
#pragma unroll
        for (int i = 0; i < 64; i++) {
            int idx = tid + i * 256;           // over 256*64
            int c = idx >> 6;
            int j = idx & 63;
            uint32_t p0 = T[(uint32_t)c * 129 + 2 * j];
            uint32_t p1 = T[(uint32_t)c * 129 + 2 * j + 1];
            size_t o = (size_t)c * NN + row0 + 2 * j;
            *(uint32_t*)(tH + o) = (p0 & 0xFFFFu) | ((p1 & 0xFFFFu) << 16);
            *(uint32_t*)(tL + o) = (p0 >> 16) | (p1 & 0xFFFF0000u);
        }
    }
}

// =================== HMMA gemm2 ==========================================
#define G2_STAGE 65536
#define G2_SMEM  (2 * G2_STAGE)

__global__ __launch_bounds__(256, 1) void k_gemm2_mma(const float* __restrict__ gc_b)
{
    extern __shared__ char smem[];
    const uint32_t sb = smem_to_u32(smem);
    const int tid = threadIdx.x;
    const int wid = tid >> 5;
    const int lane = tid & 31;
    const int row0 = blockIdx.x * 128;
    const int warpM = (wid & 3) * 32;
    const int warpN = (wid >> 2) * 64;

    float acc[2][8][4];
#pragma unroll
    for (int i = 0; i < 2; i++)
#pragma unroll
        for (int j = 0; j < 8; j++)
#pragma unroll
            for (int q = 0; q < 4; q++) acc[i][j][q] = 0.f;

    auto load = [&](int s, int buf) {
        const int m  = s >> 2;
        const int c0 = (s & 3) * 64;
        const __nv_bfloat16* A_h = g_xrh[m] + (size_t)row0 * 256;
        const __nv_bfloat16* A_l = g_xrl[m] + (size_t)row0 * 256;
        const __nv_bfloat16* B_h = g_wth + m * 32768;
        const __nv_bfloat16* B_l = g_wtl + m * 32768;
        const uint32_t st = sb + buf * G2_STAGE;
#pragma unroll
        for (int i = 0; i < 4; i++) {
            int idx = tid + i * 256;
            int row = idx >> 3;
            int c16 = idx & 7;
            uint32_t off = SWZ((uint32_t)(row * 128 + c16 * 16));
            size_t src = (size_t)row * 256 + c0 + c16 * 8;
            CP16(st + off,         A_h + src);
            CP16(st + 16384 + off, A_l + src);
            CP16(st + 32768 + off, B_h + src);
            CP16(st + 49152 + off, B_l + src);
        }
        CP_COMMIT();
    };

    load(0, 0);
    for (int s = 0; s < 16; s++) {
        if (s + 1 < 16) { load(s + 1, (s + 1) & 1); CP_WAIT1(); }
        else           { CP_WAIT0(); }
        __syncthreads();
        hmma_stage<2>(sb + (s & 1) * G2_STAGE, 16384, 32768, 49152,
                      warpM, warpN, lane, acc);
        __syncthreads();
    }

    const int qr = lane >> 2;
    const int qc = (lane & 3) * 2;
#pragma unroll
    for (int mt = 0; mt < 2; mt++)
#pragma unroll
        for (int half = 0; half < 2; half++) {
            int row = row0 + warpM + mt * 16 + half * 8 + qr;
#pragma unroll
            for (int nt = 0; nt < 8; nt++) {
                int col = warpN + nt * 8 + qc;
                float v0 = acc[mt][nt][half * 2 + 0] + gc_b[col];
                float v1 = acc[mt][nt][half * 2 + 1] + gc_b[col + 1];
                v0 = (v0 >= 0.f) ? v0 : 0.01f * v0;
                v1 = (v1 >= 0.f) ? v1 : 0.01f * v1;
                *(float2*)(g_gco + (size_t)row * 128 + col) = make_float2(v0, v1);
            }
        }
}

// ---------------- sa[b,k] reduction ---------------------------------------
__global__ __launch_bounds__(256) void k_sa(const float* __restrict__ hidden,
                                            const float* __restrict__ att_w,
                                            const float* __restrict__ att_b)
{
    const int k = blockIdx.x;
    const int b = blockIdx.y;
    const float* hb = hidden + ((size_t)(b * 4 + k) << 17);
    const int tid = threadIdx.x;

    float sum = 0.f;
    for (int i = tid; i < NN * HIDD; i += 256) {
        int n = i >> 6, h = i & 63;
        float re = hb[(n << 7) + h];
        float im = hb[(n << 7) + 64 + h];
        float c = g_cos[(k << 16) + i];
        float s = g_sin[(k << 16) + i];
        sum += (c * re - s * im) * att_w[(n << 7) + h]
             + (s * re + c * im) * att_w[(n << 7) + 64 + h];
    }
    __shared__ float red[8];
    for (int o = 16; o; o >>= 1) sum += __shfl_down_sync(0xffffffffu, sum, o);
    if ((tid & 31) == 0) red[tid >> 5] = sum;
    __syncthreads();
    if (tid < 8) {
        float v = red[tid];
        for (int o = 4; o; o >>= 1) v += __shfl_down_sync(0xffu, v, o);
        if (tid == 0) g_sa[b * 4 + k] = v + att_b[0];
    }
}

__global__ void k_softmax()
{
    int b = threadIdx.x;
    if (b >= BSZ) return;
    float s0 = g_sa[b * 4 + 0], s1 = g_sa[b * 4 + 1];
    float s2 = g_sa[b * 4 + 2], s3 = g_sa[b * 4 + 3];
    float m = fmaxf(fmaxf(s0, s1), fmaxf(s2, s3));
    float e0 = expf(s0 - m), e1 = expf(s1 - m), e2 = expf(s2 - m), e3 = expf(s3 - m);
    float inv = 1.f / (e0 + e1 + e2 + e3);
    g_wa[b * 4 + 0] = e0 * inv;
    g_wa[b * 4 + 1] = e1 * inv;
    g_wa[b * 4 + 2] = e2 * inv;
    g_wa[b * 4 + 3] = e3 * inv;
}

__global__ __launch_bounds__(256) void k_att(const float* __restrict__ hidden)
{
    int idx = blockIdx.x * 256 + threadIdx.x;
    if (idx >= BSZ * NN * DD) return;
    int d = idx & 127;
    int n = (idx >> 7) & 1023;
    int b = idx >> 17;
    int h = d & 63;
    bool isIm = d >= 64;
    float acc = 0.f;
#pragma unroll
    for (int k = 0; k < 4; k++) {
        const float* hb = hidden + ((size_t)(b * 4 + k) << 17);
        float re = hb[(n << 7) + h];
        float im = hb[(n << 7) + 64 + h];
        float c = g_cos[(k << 16) + (n << 6) + h];
        float s = g_sin[(k << 16) + (n << 6) + h];
        float v = isIm ? (s * re + c * im) : (c * re - s * im);
        acc += g_wa[b * 4 + k] * v;
    }
    g_att[idx] = acc;
}

// ---------------- final: out = gco@W + b + att (fp32 SGEMM) ---------------
__global__ __launch_bounds__(256) void k_final(const float* __restrict__ W,
                                               const float* __restrict__ bias,
                                               float* __restrict__ out)
{
    const int row0 = blockIdx.x * 64;
    __shared__ float As[16][68];
    __shared__ float Bs[16][132];
    const int tid = threadIdx.x;
    const int a_r = tid >> 2;
    const int a_c = (tid & 3) << 2;
    const int b_r = tid >> 5;
    const int b_c = (tid & 31) << 2;
    const int ty  = tid >> 4;
    const int tx  = tid & 15;

    float acc[4][8];
#pragma unroll
    for (int i = 0; i < 4; i++)
#pragma unroll
        for (int j = 0; j < 8; j++) acc[i][j] = 0.f;

    for (int k0 = 0; k0 < 128; k0 += 16) {
        float4 av = *(const float4*)(g_gco + (size_t)(row0 + a_r) * 128 + k0 + a_c);
        float4 b0 = *(const float4*)(W + (size_t)(k0 + b_r) * 128 + b_c);
        float4 b1 = *(const float4*)(W + (size_t)(k0 + b_r + 8) * 128 + b_c);
        __syncthreads();
        As[a_c + 0][a_r] = av.x; As[a_c + 1][a_r] = av.y;
        As[a_c + 2][a_r] = av.z; As[a_c + 3][a_r] = av.w;
        *(float4*)&Bs[b_r][b_c]     = b0;
        *(float4*)&Bs[b_r + 8][b_c] = b1;
        __syncthreads();
#pragma unroll
        for (int kk = 0; kk < 16; kk++) {
            float ar[4], br[8];
            *(float4*)&ar[0] = *(const float4*)&As[kk][ty * 4];
            *(float4*)&br[0] = *(const float4*)&Bs[kk][tx * 8];
            *(float4*)&br[4] = *(const float4*)&Bs[kk][tx * 8 + 4];
#pragma unroll
            for (int i = 0; i < 4; i++)
#pragma unroll
                for (int j = 0; j < 8; j++) acc[i][j] += ar[i] * br[j];
        }
    }
#pragma unroll
    for (int i = 0; i < 4; i++) {
        int rr = row0 + ty * 4 + i;
        int b  = rr >> 10;
        int n  = rr & 1023;
        size_t nh_off = (size_t)OUT0 + (((size_t)(b * 4 + 3) << 10 | n) << 7);
#pragma unroll
        for (int j = 0; j < 8; j++) {
            int col = tx * 8 + j;
            float v = acc[i][j] + bias[(size_t)n * 128 + col] + g_att[(size_t)rr * 128 + col];
            out[(size_t)rr * 128 + col] = v;
            out[nh_off + col]           = v;
        }
    }
}

__global__ __launch_bounds__(256) void k_copy(const float* __restrict__ hidden,
                                              float* __restrict__ out)
{
    int i4 = blockIdx.x * 256 + threadIdx.x;
    const int per_b = 3 * (NN * DD) / 4;
    if (i4 >= BSZ * per_b) return;
    int b  = i4 / per_b;
    int r4 = i4 - b * per_b;
    const float4* hv = (const float4*)hidden;
    float4* ov = (float4*)out;
    ov[(OUT0 / 4) + (size_t)b * 131072 + r4] = hv[(size_t)b * 131072 + 32768 + r4];
}

// ---------------- launch ---------------------------------------------------
extern "C" void kernel_launch(void* const* d_in, const int* in_sizes, int n_in,
                              void* d_out, int out_size)
{
    const float* inputs   = (const float*)d_in[0];
    const float* supports = (const float*)d_in[1];
    const float* hidden   = (const float*)d_in[2];
    const float* W        = (const float*)d_in[3];
    const float* bias     = (const float*)d_in[4];
    const float* R        = (const float*)d_in[5];
    const float* gc_w  = (const float*)d_in[6];
    const float* gc_b  = (const float*)d_in[7];
    const float* att_w = (const float*)d_in[10];
    const float* att_b = (const float*)d_in[11];
    float* out = (float*)d_out;

    static bool attrs_set = false;
    if (!attrs_set) {
        cudaFuncSetAttribute(k_cheb_mma, cudaFuncAttributeMaxDynamicSharedMemorySize, CB_SMEM);
        cudaFuncSetAttribute(k_gemm2_mma, cudaFuncAttributeMaxDynamicSharedMemorySize, G2_SMEM);
        attrs_set = true;
    }

    k_sconv<<<(BSZ * NN * NN / 4 + 255) / 256, 256>>>(supports);
    k_build_x0<<<dim3(NN / 32, CC / 32, BSZ), 256>>>(inputs, hidden);
    k_wt<<<(4 * 128 * 256 + 255) / 256, 256>>>(gc_w);
    k_cs<<<(PREK * NN * HIDD + 255) / 256, 256>>>(R);

    dim3 gC(8, BSZ);
    k_cheb_mma<<<gC, 256, CB_SMEM>>>(0);
    k_cheb_mma<<<gC, 256, CB_SMEM>>>(1);
    k_cheb_mma<<<gC, 256, CB_SMEM>>>(2);

    k_gemm2_mma<<<128, 256, G2_SMEM>>>(gc_b);

    k_sa<<<dim3(PREK, BSZ), 256>>>(hidden, att_w, att_b);
    k_softmax<<<1, 32>>>();
    k_att<<<(BSZ * NN * DD + 255) / 256, 256>>>(hidden);

    k_final<<<(BSZ * NN) / 64, 256>>>(W, bias, out);
    k_copy<<<(BSZ * 3 * NN * DD / 4 + 255) / 256, 256>>>(hidden, out);
}

// round 5
// speedup vs baseline: 2.0134x; 1.0168x over previous
#include <cuda_runtime.h>
#include <cuda_bf16.h>
#include <cstdint>

#define BSZ   16
#define NN    1024
#define HIDD  64
#define DD    128
#define CC    256
#define PREK  4

#define XSZ   (BSZ * NN * CC)
#define OUT0  (BSZ * NN * DD)

#define PHASE_SCALE ((float)(3.141592653589793 / 0.21875))

// ===================== base-ISA tensor helpers (sm_80+) =====================
__device__ __forceinline__ uint32_t smem_to_u32(const void* p) {
    uint32_t a;
    asm("{ .reg .u64 t; cvta.to.shared.u64 t, %1; cvt.u32.u64 %0, t; }" : "=r"(a) : "l"(p));
    return a;
}
__device__ __forceinline__ void ldmx4(uint32_t* r, uint32_t addr) {
    asm volatile("ldmatrix.sync.aligned.m8n8.x4.shared.b16 {%0,%1,%2,%3}, [%4];"
        : "=r"(r[0]), "=r"(r[1]), "=r"(r[2]), "=r"(r[3]) : "r"(addr));
}
__device__ __forceinline__ void mma16816(float* c, const uint32_t* a, const uint32_t* b) {
    asm volatile("mma.sync.aligned.m16n8k16.row.col.f32.bf16.bf16.f32 "
        "{%0,%1,%2,%3}, {%4,%5,%6,%7}, {%8,%9}, {%0,%1,%2,%3};"
        : "+f"(c[0]), "+f"(c[1]), "+f"(c[2]), "+f"(c[3])
        : "r"(a[0]), "r"(a[1]), "r"(a[2]), "r"(a[3]), "r"(b[0]), "r"(b[1]));
}
#define CP16(dst, src) \
    asm volatile("cp.async.cg.shared.global [%0], [%1], 16;" :: "r"(dst), "l"(src))
#define CP_COMMIT() asm volatile("cp.async.commit_group;" ::: "memory")
#define CP_WAIT1()  asm volatile("cp.async.wait_group 1;" ::: "memory")
#define CP_WAIT0()  asm volatile("cp.async.wait_group 0;" ::: "memory")
#define SWZ(off) ((off) ^ (((off) >> 3) & 0x70))

// ========================= scratch =========================
__device__ __align__(16) __nv_bfloat16 g_shi[BSZ * NN * NN];
__device__ __align__(16) __nv_bfloat16 g_slo[BSZ * NN * NN];
__device__ __align__(16) __nv_bfloat16 g_xth[3][BSZ * CC * NN];
__device__ __align__(16) __nv_bfloat16 g_xtl[3][BSZ * CC * NN];
__device__ __align__(16) __nv_bfloat16 g_xrh[4][XSZ];
__device__ __align__(16) __nv_bfloat16 g_xrl[4][XSZ];
__device__ __align__(16) __nv_bfloat16 g_wth[4 * 128 * 256];
__device__ __align__(16) __nv_bfloat16 g_wtl[4 * 128 * 256];
__device__ float g_gco[BSZ * NN * DD];
__device__ float g_cos[PREK * NN * HIDD];
__device__ float g_sin[PREK * NN * HIDD];
__device__ float g_sa[BSZ * PREK];
__device__ float g_wa[BSZ * PREK];

// ---------------- S -> bf16 hi/lo --------------------------------------
__global__ __launch_bounds__(256) void k_sconv(const float* __restrict__ S)
{
    int i = blockIdx.x * 256 + threadIdx.x;
    const int total = BSZ * NN * NN / 4;
    if (i >= total) return;
    float4 v = ((const float4*)S)[i];
    __nv_bfloat16 h0 = __float2bfloat16(v.x), h1 = __float2bfloat16(v.y);
    __nv_bfloat16 h2 = __float2bfloat16(v.z), h3 = __float2bfloat16(v.w);
    __nv_bfloat16 l0 = __float2bfloat16(v.x - __bfloat162float(h0));
    __nv_bfloat16 l1 = __float2bfloat16(v.y - __bfloat162float(h1));
    __nv_bfloat16 l2 = __float2bfloat16(v.z - __bfloat162float(h2));
    __nv_bfloat16 l3 = __float2bfloat16(v.w - __bfloat162float(h3));
    __nv_bfloat162* ph = (__nv_bfloat162*)g_shi;
    __nv_bfloat162* pl = (__nv_bfloat162*)g_slo;
    ph[i * 2]     = __nv_bfloat162(h0, h1);
    ph[i * 2 + 1] = __nv_bfloat162(h2, h3);
    pl[i * 2]     = __nv_bfloat162(l0, l1);
    pl[i * 2 + 1] = __nv_bfloat162(l2, l3);
}

// ---------------- build x0: row-major hi/lo + transposed hi/lo ----------
__global__ __launch_bounds__(256) void k_build_x0(const float* __restrict__ inputs,
                                                  const float* __restrict__ hidden)
{
    __shared__ float tile[32][33];
    const int n0 = blockIdx.x * 32;
    const int c0 = blockIdx.y * 32;
    const int b  = blockIdx.z;
    const int lane = threadIdx.x & 31;
    const int wrp  = threadIdx.x >> 5;

#pragma unroll
    for (int r = 0; r < 4; r++) {
        int nl = wrp * 4 + r;
        int n = n0 + nl;
        int c = c0 + lane;
        float v;
        if (c < 64)        v = inputs[((size_t)(b * NN + n)) * 128 + c];
        else if (c < 128)  v = hidden[(((size_t)(b * 4 + 3) * NN + n)) * 128 + (c - 64)];
        else if (c < 192)  v = inputs[((size_t)(b * NN + n)) * 128 + (c - 128 + 64)];
        else               v = hidden[(((size_t)(b * 4 + 3) * NN + n)) * 128 + (c - 192 + 64)];
        __nv_bfloat16 h = __float2bfloat16(v);
        __nv_bfloat16 l = __float2bfloat16(v - __bfloat162float(h));
        size_t o = ((size_t)(b * NN + n)) * CC + c;
        g_xrh[0][o] = h;
        g_xrl[0][o] = l;
        tile[nl][lane] = v;
    }
    __syncthreads();
#pragma unroll
    for (int r = 0; r < 4; r++) {
        int cl = wrp * 4 + r;
        float v = tile[lane][cl];
        __nv_bfloat16 h = __float2bfloat16(v);
        __nv_bfloat16 l = __float2bfloat16(v - __bfloat162float(h));
        size_t o = ((size_t)b * CC + c0 + cl) * NN + n0 + lane;
        g_xth[0][o] = h;
        g_xtl[0][o] = l;
    }
}

// ---------------- gc_w -> wtT hi/lo [m][d][c] ---------------------------
__global__ __launch_bounds__(256) void k_wt(const float* __restrict__ gc_w)
{
    int i = blockIdx.x * 256 + threadIdx.x;
    if (i >= 4 * 128 * 256) return;
    int c = i & 255;
    int d = (i >> 8) & 127;
    int m = i >> 15;
    float v = gc_w[(size_t)d * 1024 + c * 4 + m];
    __nv_bfloat16 h = __float2bfloat16(v);
    g_wth[i] = h;
    g_wtl[i] = __float2bfloat16(v - __bfloat162float(h));
}

// ---------------- cos/sin tables ----------------------------------------
__global__ __launch_bounds__(256) void k_cs(const float* __restrict__ R)
{
    int i = blockIdx.x * 256 + threadIdx.x;
    if (i >= PREK * NN * HIDD) return;
    float ph = R[i] * PHASE_SCALE;
    float s, c;
    sincosf(ph, &s, &c);
    g_cos[i] = c;
    g_sin[i] = s;
}

// =================== HMMA Chebyshev GEMM v3 (512 threads) ================
// grid (8 mt, 16 b) = 128 CTAs. CTA tile 128x256, BK=64, 16 warps (4Mx4N),
// warp tile 32x64. stage 96KB x2 = 192KB.
#define CB_STAGE 98304
#define CB_SMEM  (2 * CB_STAGE)

__device__ __forceinline__ void cheb_load512(uint32_t sb, char* smem, int buf, int tid,
    const __nv_bfloat16* A_h, const __nv_bfloat16* A_l,
    const __nv_bfloat16* B_h, const __nv_bfloat16* B_l, int k0)
{
    const uint32_t st = sb + buf * CB_STAGE;
#pragma unroll
    for (int i = 0; i < 2; i++) {                    // A: 128 rows x 8 chunks
        int idx = tid + i * 512;
        int row = idx >> 3;
        int c16 = idx & 7;
        uint32_t off = SWZ((uint32_t)(row * 128 + c16 * 16));
        size_t src = (size_t)row * 1024 + k0 + c16 * 8;
        CP16(st + off,         A_h + src);
        CP16(st + 16384 + off, A_l + src);
    }
#pragma unroll
    for (int i = 0; i < 4; i++) {                    // B: 256 rows x 8 chunks
        int idx = tid + i * 512;
        int row = idx >> 3;
        int c16 = idx & 7;
        uint32_t off = SWZ((uint32_t)(row * 128 + c16 * 16));
        size_t src = (size_t)row * 1024 + k0 + c16 * 8;
        CP16(st + 32768 + off, B_h + src);
        CP16(st + 65536 + off, B_l + src);
    }
    CP_COMMIT();
}

__device__ __forceinline__ void hmma_stage512(uint32_t st, int warpM, int warpN,
                                              int lane, float acc[2][8][4])
{
    const int arow = lane & 15;
    const int acol = (lane >> 4) << 4;
    const int g    = lane >> 3;
    const int brow = ((g >> 1) << 3) + (lane & 7);
    const int bcol = (g & 1) << 4;
#pragma unroll
    for (int ks = 0; ks < 4; ks++) {
        uint32_t ah[2][4], al[2][4];
#pragma unroll
        for (int mt = 0; mt < 2; mt++) {
            uint32_t off = SWZ((uint32_t)((warpM + mt * 16 + arow) * 128 + ks * 32 + acol));
            ldmx4(ah[mt], st + off);
            ldmx4(al[mt], st + 16384 + off);
        }
#pragma unroll
        for (int np = 0; np < 4; np++) {
            uint32_t bh[4], bl[4];
            uint32_t off = SWZ((uint32_t)((warpN + np * 16 + brow) * 128 + ks * 32 + bcol));
            ldmx4(bh, st + 32768 + off);
            ldmx4(bl, st + 65536 + off);
#pragma unroll
            for (int mt = 0; mt < 2; mt++) {
                mma16816(acc[mt][np * 2],     ah[mt], &bh[0]);
                mma16816(acc[mt][np * 2],     ah[mt], &bl[0]);
                mma16816(acc[mt][np * 2],     al[mt], &bh[0]);
                mma16816(acc[mt][np * 2 + 1], ah[mt], &bh[2]);
                mma16816(acc[mt][np * 2 + 1], ah[mt], &bl[2]);
                mma16816(acc[mt][np * 2 + 1], al[mt], &bh[2]);
            }
        }
    }
}

__global__ __launch_bounds__(512, 1) void k_cheb_mma(int hop)
{
    extern __shared__ char smem[];
    const uint32_t sb = smem_to_u32(smem);
    const int tid = threadIdx.x;
    const int wid = tid >> 5;
    const int lane = tid & 31;
    const int row0 = blockIdx.x * 128;
    const int b = blockIdx.y;
    const int warpM = (wid & 3) * 32;      // 4 M groups of 32
    const int warpN = (wid >> 2) * 64;     // 4 N groups of 64

    const __nv_bfloat16* A_h = g_shi + ((size_t)b * NN + row0) * NN;
    const __nv_bfloat16* A_l = g_slo + ((size_t)b * NN + row0) * NN;
    const __nv_bfloat16* B_h = g_xth[hop] + (size_t)b * CC * NN;
    const __nv_bfloat16* B_l = g_xtl[hop] + (size_t)b * CC * NN;

    float acc[2][8][4];
#pragma unroll
    for (int i = 0; i < 2; i++)
#pragma unroll
        for (int j = 0; j < 8; j++)
#pragma unroll
            for (int q = 0; q < 4; q++) acc[i][j][q] = 0.f;

    cheb_load512(sb, smem, 0, tid, A_h, A_l, B_h, B_l, 0);

    for (int s = 0; s < 16; s++) {
        if (s + 1 < 16) {
            cheb_load512(sb, smem, (s + 1) & 1, tid, A_h, A_l, B_h, B_l, (s + 1) * 64);
            CP_WAIT1();
        } else {
            CP_WAIT0();
        }
        __syncthreads();
        hmma_stage512(sb + (s & 1) * CB_STAGE, warpM, warpN, lane, acc);
        __syncthreads();
    }

    // ---------------- epilogue ----------------
    const int qr = lane >> 2;
    const int qc = (lane & 3) * 2;
    const size_t rmBase = (size_t)b * NN * CC;
    const __nv_bfloat16* pH = (hop >= 1) ? g_xrh[hop - 1] : nullptr;
    const __nv_bfloat16* pL = (hop >= 1) ? g_xrl[hop - 1] : nullptr;
    __nv_bfloat16* oH = g_xrh[hop + 1];
    __nv_bfloat16* oL = g_xrl[hop + 1];

    uint32_t* T = (uint32_t*)smem;       // [256][129] packed (hi,lo)

#pragma unroll
    for (int mt = 0; mt < 2; mt++)
#pragma unroll
        for (int half = 0; half < 2; half++) {
            int rloc = warpM + mt * 16 + half * 8 + qr;        // 0..127
            int row = row0 + rloc;
#pragma unroll
            for (int nt = 0; nt < 8; nt++) {
                int col = warpN + nt * 8 + qc;                  // 0..255
                float v0 = acc[mt][nt][half * 2 + 0];
                float v1 = acc[mt][nt][half * 2 + 1];
                size_t idx = rmBase + (size_t)row * CC + col;
                if (hop >= 1) {
                    __nv_bfloat162 phv = *(const __nv_bfloat162*)(pH + idx);
                    __nv_bfloat162 plv = *(const __nv_bfloat162*)(pL + idx);
                    v0 = 2.f * v0 - (__bfloat162float(phv.x) + __bfloat162float(plv.x));
                    v1 = 2.f * v1 - (__bfloat162float(phv.y) + __bfloat162float(plv.y));
                }
                __nv_bfloat16 h0 = __float2bfloat16(v0);
                __nv_bfloat16 l0 = __float2bfloat16(v0 - __bfloat162float(h0));
                __nv_bfloat16 h1 = __float2bfloat16(v1);
                __nv_bfloat16 l1 = __float2bfloat16(v1 - __bfloat162float(h1));
                *(__nv_bfloat162*)(oH + idx) = __nv_bfloat162(h0, h1);
                *(__nv_bfloat162*)(oL + idx) = __nv_bfloat162(l0, l1);
                if (hop < 2) {
                    T[(uint32_t)col * 129 + rloc] =
                        (uint32_t)__bfloat16_as_ushort(h0) |
                        ((uint32_t)__bfloat16_as_ushort(l0) << 16);
                    T[(uint32_t)(col + 1) * 129 + rloc] =
                        (uint32_t)__bfloat16_as_ushort(h1) |
                        ((uint32_t)__bfloat16_as_ushort(l1) << 16);
                }
            }
        }

    if (hop < 2) {
        __syncthreads();
        __nv_bfloat16* tH = g_xth[hop + 1] + (size_t)b * CC * NN;
        __nv_bfloat16* tL = g_xtl[hop + 1] + (size_t)b * CC * NN;
#pragma unroll
        for (int i = 0; i < 32; i++) {
            int idx = tid + i * 512;           // over 256*64
            int c = idx >> 6;
            int j = idx & 63;
            uint32_t p0 = T[(uint32_t)c * 129 + 2 * j];
            uint32_t p1 = T[(uint32_t)c * 129 + 2 * j + 1];
            size_t o = (size_t)c * NN + row0 + 2 * j;
            *(uint32_t*)(tH + o) = (p0 & 0xFFFFu) | ((p1 & 0xFFFFu) << 16);
            *(uint32_t*)(tL + o) = (p0 >> 16) | (p1 & 0xFFFF0000u);
        }
    }
}

// =================== HMMA gemm2 ==========================================
#define G2_STAGE 65536
#define G2_SMEM  (2 * G2_STAGE)

template<int MT>
__device__ __forceinline__ void hmma_stage(uint32_t st, uint32_t aLoOff,
                                           uint32_t bHiOff, uint32_t bLoOff,
                                           int warpM, int warpN, int lane,
                                           float (*acc)[8][4])
{
    const int arow = lane & 15;
    const int acol = (lane >> 4) << 4;
    const int g    = lane >> 3;
    const int brow = ((g >> 1) << 3) + (lane & 7);
    const int bcol = (g & 1) << 4;
#pragma unroll
    for (int ks = 0; ks < 4; ks++) {
        uint32_t ah[MT][4], al[MT][4];
#pragma unroll
        for (int mt = 0; mt < MT; mt++) {
            uint32_t off = SWZ((uint32_t)((warpM + mt * 16 + arow) * 128 + ks * 32 + acol));
            ldmx4(ah[mt], st + off);
            ldmx4(al[mt], st + aLoOff + off);
        }
#pragma unroll
        for (int np = 0; np < 4; np++) {
            uint32_t bh[4], bl[4];
            uint32_t off = SWZ((uint32_t)((warpN + np * 16 + brow) * 128 + ks * 32 + bcol));
            ldmx4(bh, st + bHiOff + off);
            ldmx4(bl, st + bLoOff + off);
#pragma unroll
            for (int mt = 0; mt < MT; mt++) {
                mma16816(acc[mt][np * 2],     ah[mt], &bh[0]);
                mma16816(acc[mt][np * 2],     ah[mt], &bl[0]);
                mma16816(acc[mt][np * 2],     al[mt], &bh[0]);
                mma16816(acc[mt][np * 2 + 1], ah[mt], &bh[2]);
                mma16816(acc[mt][np * 2 + 1], ah[mt], &bl[2]);
                mma16816(acc[mt][np * 2 + 1], al[mt], &bh[2]);
            }
        }
    }
}

__global__ __launch_bounds__(256, 1) void k_gemm2_mma(const float* __restrict__ gc_b)
{
    extern __shared__ char smem[];
    const uint32_t sb = smem_to_u32(smem);
    const int tid = threadIdx.x;
    const int wid = tid >> 5;
    const int lane = tid & 31;
    const int row0 = blockIdx.x * 128;
    const int warpM = (wid & 3) * 32;
    const int warpN = (wid >> 2) * 64;

    float acc[2][8][4];
#pragma unroll
    for (int i = 0; i < 2; i++)
#pragma unroll
        for (int j = 0; j < 8; j++)
#pragma unroll
            for (int q = 0; q < 4; q++) acc[i][j][q] = 0.f;

    auto load = [&](int s, int buf) {
        const int m  = s >> 2;
        const int c0 = (s & 3) * 64;
        const __nv_bfloat16* A_h = g_xrh[m] + (size_t)row0 * 256;
        const __nv_bfloat16* A_l = g_xrl[m] + (size_t)row0 * 256;
        const __nv_bfloat16* B_h = g_wth + m * 32768;
        const __nv_bfloat16* B_l = g_wtl + m * 32768;
        const uint32_t st = sb + buf * G2_STAGE;
#pragma unroll
        for (int i = 0; i < 4; i++) {
            int idx = tid + i * 256;
            int row = idx >> 3;
            int c16 = idx & 7;
            uint32_t off = SWZ((uint32_t)(row * 128 + c16 * 16));
            size_t src = (size_t)row * 256 + c0 + c16 * 8;
            CP16(st + off,         A_h + src);
            CP16(st + 16384 + off, A_l + src);
            CP16(st + 32768 + off, B_h + src);
            CP16(st + 49152 + off, B_l + src);
        }
        CP_COMMIT();
    };

    load(0, 0);
    for (int s = 0; s < 16; s++) {
        if (s + 1 < 16) { load(s + 1, (s + 1) & 1); CP_WAIT1(); }
        else           { CP_WAIT0(); }
        __syncthreads();
        hmma_stage<2>(sb + (s & 1) * G2_STAGE, 16384, 32768, 49152,
                      warpM, warpN, lane, acc);
        __syncthreads();
    }

    const int qr = lane >> 2;
    const int qc = (lane & 3) * 2;
#pragma unroll
    for (int mt = 0; mt < 2; mt++)
#pragma unroll
        for (int half = 0; half < 2; half++) {
            int row = row0 + warpM + mt * 16 + half * 8 + qr;
#pragma unroll
            for (int nt = 0; nt < 8; nt++) {
                int col = warpN + nt * 8 + qc;
                float v0 = acc[mt][nt][half * 2 + 0] + gc_b[col];
                float v1 = acc[mt][nt][half * 2 + 1] + gc_b[col + 1];
                v0 = (v0 >= 0.f) ? v0 : 0.01f * v0;
                v1 = (v1 >= 0.f) ? v1 : 0.01f * v1;
                *(float2*)(g_gco + (size_t)row * 128 + col) = make_float2(v0, v1);
            }
        }
}

// ---------------- sa[b,k] reduction ---------------------------------------
__global__ __launch_bounds__(256) void k_sa(const float* __restrict__ hidden,
                                            const float* __restrict__ att_w,
                                            const float* __restrict__ att_b)
{
    const int k = blockIdx.x;
    const int b = blockIdx.y;
    const float* hb = hidden + ((size_t)(b * 4 + k) << 17);
    const int tid = threadIdx.x;

    float sum = 0.f;
    for (int i = tid; i < NN * HIDD; i += 256) {
        int n = i >> 6, h = i & 63;
        float re = hb[(n << 7) + h];
        float im = hb[(n << 7) + 64 + h];
        float c = g_cos[(k << 16) + i];
        float s = g_sin[(k << 16) + i];
        sum += (c * re - s * im) * att_w[(n << 7) + h]
             + (s * re + c * im) * att_w[(n << 7) + 64 + h];
    }
    __shared__ float red[8];
    for (int o = 16; o; o >>= 1) sum += __shfl_down_sync(0xffffffffu, sum, o);
    if ((tid & 31) == 0) red[tid >> 5] = sum;
    __syncthreads();
    if (tid < 8) {
        float v = red[tid];
        for (int o = 4; o; o >>= 1) v += __shfl_down_sync(0xffu, v, o);
        if (tid == 0) g_sa[b * 4 + k] = v + att_b[0];
    }
}

__global__ void k_softmax()
{
    int b = threadIdx.x;
    if (b >= BSZ) return;
    float s0 = g_sa[b * 4 + 0], s1 = g_sa[b * 4 + 1];
    float s2 = g_sa[b * 4 + 2], s3 = g_sa[b * 4 + 3];
    float m = fmaxf(fmaxf(s0, s1), fmaxf(s2, s3));
    float e0 = expf(s0 - m), e1 = expf(s1 - m), e2 = expf(s2 - m), e3 = expf(s3 - m);
    float inv = 1.f / (e0 + e1 + e2 + e3);
    g_wa[b * 4 + 0] = e0 * inv;
    g_wa[b * 4 + 1] = e1 * inv;
    g_wa[b * 4 + 2] = e2 * inv;
    g_wa[b * 4 + 3] = e3 * inv;
}

// ---------------- final: out = gco@W + b + att (att fused inline) ---------
__global__ __launch_bounds__(256) void k_final(const float* __restrict__ W,
                                               const float* __restrict__ bias,
                                               const float* __restrict__ hidden,
                                               float* __restrict__ out)
{
    const int row0 = blockIdx.x * 64;
    __shared__ float As[16][68];
    __shared__ float Bs[16][132];
    const int tid = threadIdx.x;
    const int a_r = tid >> 2;
    const int a_c = (tid & 3) << 2;
    const int b_r = tid >> 5;
    const int b_c = (tid & 31) << 2;
    const int ty  = tid >> 4;
    const int tx  = tid & 15;

    float acc[4][8];
#pragma unroll
    for (int i = 0; i < 4; i++)
#pragma unroll
        for (int j = 0; j < 8; j++) acc[i][j] = 0.f;

    for (int k0 = 0; k0 < 128; k0 += 16) {
        float4 av = *(const float4*)(g_gco + (size_t)(row0 + a_r) * 128 + k0 + a_c);
        float4 b0 = *(const float4*)(W + (size_t)(k0 + b_r) * 128 + b_c);
        float4 b1 = *(const float4*)(W + (size_t)(k0 + b_r + 8) * 128 + b_c);
        __syncthreads();
        As[a_c + 0][a_r] = av.x; As[a_c + 1][a_r] = av.y;
        As[a_c + 2][a_r] = av.z; As[a_c + 3][a_r] = av.w;
        *(float4*)&Bs[b_r][b_c]     = b0;
        *(float4*)&Bs[b_r + 8][b_c] = b1;
        __syncthreads();
#pragma unroll
        for (int kk = 0; kk < 16; kk++) {
            float ar[4], br[8];
            *(float4*)&ar[0] = *(const float4*)&As[kk][ty * 4];
            *(float4*)&br[0] = *(const float4*)&Bs[kk][tx * 8];
            *(float4*)&br[4] = *(const float4*)&Bs[kk][tx * 8 + 4];
#pragma unroll
            for (int i = 0; i < 4; i++)
#pragma unroll
                for (int j = 0; j < 8; j++) acc[i][j] += ar[i] * br[j];
        }
    }

    const bool isIm = (tx >= 8);               // cols tx*8..tx*8+7 same half
#pragma unroll
    for (int i = 0; i < 4; i++) {
        int rr = row0 + ty * 4 + i;
        int b  = rr >> 10;
        int n  = rr & 1023;
        size_t nh_off = (size_t)OUT0 + (((size_t)(b * 4 + 3) << 10 | n) << 7);
        float wa0 = g_wa[b * 4 + 0], wa1 = g_wa[b * 4 + 1];
        float wa2 = g_wa[b * 4 + 2], wa3 = g_wa[b * 4 + 3];
        float was[4] = {wa0, wa1, wa2, wa3};
#pragma unroll
        for (int j = 0; j < 8; j++) {
            int col = tx * 8 + j;
            int h = col & 63;
            float att = 0.f;
#pragma unroll
            for (int k = 0; k < 4; k++) {
                const float* hb = hidden + ((size_t)(b * 4 + k) << 17);
                float re = hb[(n << 7) + h];
                float im = hb[(n << 7) + 64 + h];
                float c = g_cos[(k << 16) + (n << 6) + h];
                float s = g_sin[(k << 16) + (n << 6) + h];
                float v = isIm ? (s * re + c * im) : (c * re - s * im);
                att += was[k] * v;
            }
            float v = acc[i][j] + bias[(size_t)n * 128 + col] + att;
            out[(size_t)rr * 128 + col] = v;
            out[nh_off + col]           = v;
        }
    }
}

__global__ __launch_bounds__(256) void k_copy(const float* __restrict__ hidden,
                                              float* __restrict__ out)
{
    int i4 = blockIdx.x * 256 + threadIdx.x;
    const int per_b = 3 * (NN * DD) / 4;
    if (i4 >= BSZ * per_b) return;
    int b  = i4 / per_b;
    int r4 = i4 - b * per_b;
    const float4* hv = (const float4*)hidden;
    float4* ov = (float4*)out;
    ov[(OUT0 / 4) + (size_t)b * 131072 + r4] = hv[(size_t)b * 131072 + 32768 + r4];
}

// ---------------- launch ---------------------------------------------------
extern "C" void kernel_launch(void* const* d_in, const int* in_sizes, int n_in,
                              void* d_out, int out_size)
{
    const float* inputs   = (const float*)d_in[0];
    const float* supports = (const float*)d_in[1];
    const float* hidden   = (const float*)d_in[2];
    const float* W        = (const float*)d_in[3];
    const float* bias     = (const float*)d_in[4];
    const float* R        = (const float*)d_in[5];
    const float* gc_w  = (const float*)d_in[6];
    const float* gc_b  = (const float*)d_in[7];
    const float* att_w = (const float*)d_in[10];
    const float* att_b = (const float*)d_in[11];
    float* out = (float*)d_out;

    static bool attrs_set = false;
    if (!attrs_set) {
        cudaFuncSetAttribute(k_cheb_mma, cudaFuncAttributeMaxDynamicSharedMemorySize, CB_SMEM);
        cudaFuncSetAttribute(k_gemm2_mma, cudaFuncAttributeMaxDynamicSharedMemorySize, G2_SMEM);
        attrs_set = true;
    }

    // order chosen so ncu (-s 5 -c 1, ~2 harness pre-launches) captures cheb
    k_sconv<<<(BSZ * NN * NN / 4 + 255) / 256, 256>>>(supports);
    k_build_x0<<<dim3(NN / 32, CC / 32, BSZ), 256>>>(inputs, hidden);

    dim3 gC(8, BSZ);
    k_cheb_mma<<<gC, 512, CB_SMEM>>>(0);
    k_cheb_mma<<<gC, 512, CB_SMEM>>>(1);
    k_cheb_mma<<<gC, 512, CB_SMEM>>>(2);

    k_wt<<<(4 * 128 * 256 + 255) / 256, 256>>>(gc_w);
    k_cs<<<(PREK * NN * HIDD + 255) / 256, 256>>>(R);

    k_gemm2_mma<<<128, 256, G2_SMEM>>>(gc_b);

    k_sa<<<dim3(PREK, BSZ), 256>>>(hidden, att_w, att_b);
    k_softmax<<<1, 32>>>();

    k_final<<<(BSZ * NN) / 64, 256>>>(W, bias, hidden, out);
    k_copy<<<(BSZ * 3 * NN * DD / 4 + 255) / 256, 256>>>(hidden, out);
}

// round 6
// speedup vs baseline: 2.0234x; 1.0049x over previous
#include <cuda_runtime.h>
#include <cuda_bf16.h>
#include <cstdint>

#define BSZ   16
#define NN    1024
#define HIDD  64
#define DD    128
#define CC    256
#define PREK  4

#define XSZ   (BSZ * NN * CC)
#define OUT0  (BSZ * NN * DD)

#define PHASE_SCALE ((float)(3.141592653589793 / 0.21875))

// ===================== base-ISA tensor helpers (sm_80+) =====================
__device__ __forceinline__ uint32_t smem_to_u32(const void* p) {
    uint32_t a;
    asm("{ .reg .u64 t; cvta.to.shared.u64 t, %1; cvt.u32.u64 %0, t; }" : "=r"(a) : "l"(p));
    return a;
}
__device__ __forceinline__ void ldmx4(uint32_t* r, uint32_t addr) {
    asm volatile("ldmatrix.sync.aligned.m8n8.x4.shared.b16 {%0,%1,%2,%3}, [%4];"
        : "=r"(r[0]), "=r"(r[1]), "=r"(r[2]), "=r"(r[3]) : "r"(addr));
}
__device__ __forceinline__ void mma16816(float* c, const uint32_t* a, const uint32_t* b) {
    asm volatile("mma.sync.aligned.m16n8k16.row.col.f32.bf16.bf16.f32 "
        "{%0,%1,%2,%3}, {%4,%5,%6,%7}, {%8,%9}, {%0,%1,%2,%3};"
        : "+f"(c[0]), "+f"(c[1]), "+f"(c[2]), "+f"(c[3])
        : "r"(a[0]), "r"(a[1]), "r"(a[2]), "r"(a[3]), "r"(b[0]), "r"(b[1]));
}
#define CP16(dst, src) \
    asm volatile("cp.async.cg.shared.global [%0], [%1], 16;" :: "r"(dst), "l"(src))
#define CP_COMMIT() asm volatile("cp.async.commit_group;" ::: "memory")
#define CP_WAIT0()  asm volatile("cp.async.wait_group 0;" ::: "memory")
#define SWZ(off) ((off) ^ (((off) >> 3) & 0x70))

// ========================= scratch =========================
__device__ __align__(16) __nv_bfloat16 g_shi[BSZ * NN * NN];
__device__ __align__(16) __nv_bfloat16 g_slo[BSZ * NN * NN];
__device__ __align__(16) __nv_bfloat16 g_xth[3][BSZ * CC * NN];
__device__ __align__(16) __nv_bfloat16 g_xtl[3][BSZ * CC * NN];
__device__ __align__(16) __nv_bfloat16 g_xrh[4][XSZ];
__device__ __align__(16) __nv_bfloat16 g_xrl[4][XSZ];
__device__ __align__(16) __nv_bfloat16 g_wth[4 * 128 * 256];
__device__ __align__(16) __nv_bfloat16 g_wtl[4 * 128 * 256];
__device__ float g_gco[BSZ * NN * DD];
__device__ float g_cos[PREK * NN * HIDD];
__device__ float g_sin[PREK * NN * HIDD];
__device__ float g_sa[BSZ * PREK];
__device__ float g_wa[BSZ * PREK];

// ---------------- S -> bf16 hi/lo --------------------------------------
__global__ __launch_bounds__(256) void k_sconv(const float* __restrict__ S)
{
    int i = blockIdx.x * 256 + threadIdx.x;
    const int total = BSZ * NN * NN / 4;
    if (i >= total) return;
    float4 v = ((const float4*)S)[i];
    __nv_bfloat16 h0 = __float2bfloat16(v.x), h1 = __float2bfloat16(v.y);
    __nv_bfloat16 h2 = __float2bfloat16(v.z), h3 = __float2bfloat16(v.w);
    __nv_bfloat16 l0 = __float2bfloat16(v.x - __bfloat162float(h0));
    __nv_bfloat16 l1 = __float2bfloat16(v.y - __bfloat162float(h1));
    __nv_bfloat16 l2 = __float2bfloat16(v.z - __bfloat162float(h2));
    __nv_bfloat16 l3 = __float2bfloat16(v.w - __bfloat162float(h3));
    __nv_bfloat162* ph = (__nv_bfloat162*)g_shi;
    __nv_bfloat162* pl = (__nv_bfloat162*)g_slo;
    ph[i * 2]     = __nv_bfloat162(h0, h1);
    ph[i * 2 + 1] = __nv_bfloat162(h2, h3);
    pl[i * 2]     = __nv_bfloat162(l0, l1);
    pl[i * 2 + 1] = __nv_bfloat162(l2, l3);
}

// ---------------- build x0: row-major hi/lo + transposed hi/lo ----------
__global__ __launch_bounds__(256) void k_build_x0(const float* __restrict__ inputs,
                                                  const float* __restrict__ hidden)
{
    __shared__ float tile[32][33];
    const int n0 = blockIdx.x * 32;
    const int c0 = blockIdx.y * 32;
    const int b  = blockIdx.z;
    const int lane = threadIdx.x & 31;
    const int wrp  = threadIdx.x >> 5;

#pragma unroll
    for (int r = 0; r < 4; r++) {
        int nl = wrp * 4 + r;
        int n = n0 + nl;
        int c = c0 + lane;
        float v;
        if (c < 64)        v = inputs[((size_t)(b * NN + n)) * 128 + c];
        else if (c < 128)  v = hidden[(((size_t)(b * 4 + 3) * NN + n)) * 128 + (c - 64)];
        else if (c < 192)  v = inputs[((size_t)(b * NN + n)) * 128 + (c - 128 + 64)];
        else               v = hidden[(((size_t)(b * 4 + 3) * NN + n)) * 128 + (c - 192 + 64)];
        __nv_bfloat16 h = __float2bfloat16(v);
        __nv_bfloat16 l = __float2bfloat16(v - __bfloat162float(h));
        size_t o = ((size_t)(b * NN + n)) * CC + c;
        g_xrh[0][o] = h;
        g_xrl[0][o] = l;
        tile[nl][lane] = v;
    }
    __syncthreads();
#pragma unroll
    for (int r = 0; r < 4; r++) {
        int cl = wrp * 4 + r;
        float v = tile[lane][cl];
        __nv_bfloat16 h = __float2bfloat16(v);
        __nv_bfloat16 l = __float2bfloat16(v - __bfloat162float(h));
        size_t o = ((size_t)b * CC + c0 + cl) * NN + n0 + lane;
        g_xth[0][o] = h;
        g_xtl[0][o] = l;
    }
}

// ---------------- gc_w -> wtT hi/lo [m][d][c] ---------------------------
__global__ __launch_bounds__(256) void k_wt(const float* __restrict__ gc_w)
{
    int i = blockIdx.x * 256 + threadIdx.x;
    if (i >= 4 * 128 * 256) return;
    int c = i & 255;
    int d = (i >> 8) & 127;
    int m = i >> 15;
    float v = gc_w[(size_t)d * 1024 + c * 4 + m];
    __nv_bfloat16 h = __float2bfloat16(v);
    g_wth[i] = h;
    g_wtl[i] = __float2bfloat16(v - __bfloat162float(h));
}

// ---------------- cos/sin tables ----------------------------------------
__global__ __launch_bounds__(256) void k_cs(const float* __restrict__ R)
{
    int i = blockIdx.x * 256 + threadIdx.x;
    if (i >= PREK * NN * HIDD) return;
    float ph = R[i] * PHASE_SCALE;
    float s, c;
    sincosf(ph, &s, &c);
    g_cos[i] = c;
    g_sin[i] = s;
}

// =================== HMMA Chebyshev GEMM (512 thr, 1-sync pipeline) ======
#define CB_STAGE 98304
#define CB_SMEM  (2 * CB_STAGE)

__device__ __forceinline__ void cheb_load512(uint32_t sb, int buf, int tid,
    const __nv_bfloat16* A_h, const __nv_bfloat16* A_l,
    const __nv_bfloat16* B_h, const __nv_bfloat16* B_l, int k0)
{
    const uint32_t st = sb + buf * CB_STAGE;
#pragma unroll
    for (int i = 0; i < 2; i++) {
        int idx = tid + i * 512;
        int row = idx >> 3;
        int c16 = idx & 7;
        uint32_t off = SWZ((uint32_t)(row * 128 + c16 * 16));
        size_t src = (size_t)row * 1024 + k0 + c16 * 8;
        CP16(st + off,         A_h + src);
        CP16(st + 16384 + off, A_l + src);
    }
#pragma unroll
    for (int i = 0; i < 4; i++) {
        int idx = tid + i * 512;
        int row = idx >> 3;
        int c16 = idx & 7;
        uint32_t off = SWZ((uint32_t)(row * 128 + c16 * 16));
        size_t src = (size_t)row * 1024 + k0 + c16 * 8;
        CP16(st + 32768 + off, B_h + src);
        CP16(st + 65536 + off, B_l + src);
    }
    CP_COMMIT();
}

__device__ __forceinline__ void hmma_stage512(uint32_t st, int warpM, int warpN,
                                              int lane, float acc[2][8][4])
{
    const int arow = lane & 15;
    const int acol = (lane >> 4) << 4;
    const int g    = lane >> 3;
    const int brow = ((g >> 1) << 3) + (lane & 7);
    const int bcol = (g & 1) << 4;
#pragma unroll
    for (int ks = 0; ks < 4; ks++) {
        uint32_t ah[2][4], al[2][4];
#pragma unroll
        for (int mt = 0; mt < 2; mt++) {
            uint32_t off = SWZ((uint32_t)((warpM + mt * 16 + arow) * 128 + ks * 32 + acol));
            ldmx4(ah[mt], st + off);
            ldmx4(al[mt], st + 16384 + off);
        }
#pragma unroll
        for (int np = 0; np < 4; np++) {
            uint32_t bh[4], bl[4];
            uint32_t off = SWZ((uint32_t)((warpN + np * 16 + brow) * 128 + ks * 32 + bcol));
            ldmx4(bh, st + 32768 + off);
            ldmx4(bl, st + 65536 + off);
#pragma unroll
            for (int mt = 0; mt < 2; mt++) {
                mma16816(acc[mt][np * 2],     ah[mt], &bh[0]);
                mma16816(acc[mt][np * 2],     ah[mt], &bl[0]);
                mma16816(acc[mt][np * 2],     al[mt], &bh[0]);
                mma16816(acc[mt][np * 2 + 1], ah[mt], &bh[2]);
                mma16816(acc[mt][np * 2 + 1], ah[mt], &bl[2]);
                mma16816(acc[mt][np * 2 + 1], al[mt], &bh[2]);
            }
        }
    }
}

__global__ __launch_bounds__(512, 1) void k_cheb_mma(int hop)
{
    extern __shared__ char smem[];
    const uint32_t sb = smem_to_u32(smem);
    const int tid = threadIdx.x;
    const int wid = tid >> 5;
    const int lane = tid & 31;
    const int row0 = blockIdx.x * 128;
    const int b = blockIdx.y;
    const int warpM = (wid & 3) * 32;
    const int warpN = (wid >> 2) * 64;

    const __nv_bfloat16* A_h = g_shi + ((size_t)b * NN + row0) * NN;
    const __nv_bfloat16* A_l = g_slo + ((size_t)b * NN + row0) * NN;
    const __nv_bfloat16* B_h = g_xth[hop] + (size_t)b * CC * NN;
    const __nv_bfloat16* B_l = g_xtl[hop] + (size_t)b * CC * NN;

    float acc[2][8][4];
#pragma unroll
    for (int i = 0; i < 2; i++)
#pragma unroll
        for (int j = 0; j < 8; j++)
#pragma unroll
            for (int q = 0; q < 4; q++) acc[i][j][q] = 0.f;

    cheb_load512(sb, 0, tid, A_h, A_l, B_h, B_l, 0);

    // single-barrier pipeline: WAIT -> BAR -> issue next load -> compute
    for (int s = 0; s < 16; s++) {
        CP_WAIT0();
        __syncthreads();
        if (s + 1 < 16)
            cheb_load512(sb, (s + 1) & 1, tid, A_h, A_l, B_h, B_l, (s + 1) * 64);
        hmma_stage512(sb + (s & 1) * CB_STAGE, warpM, warpN, lane, acc);
    }
    __syncthreads();   // protect smem reuse (transpose buffer)

    // ---------------- epilogue ----------------
    const int qr = lane >> 2;
    const int qc = (lane & 3) * 2;
    const size_t rmBase = (size_t)b * NN * CC;
    const __nv_bfloat16* pH = (hop >= 1) ? g_xrh[hop - 1] : nullptr;
    const __nv_bfloat16* pL = (hop >= 1) ? g_xrl[hop - 1] : nullptr;
    __nv_bfloat16* oH = g_xrh[hop + 1];
    __nv_bfloat16* oL = g_xrl[hop + 1];

    uint32_t* T = (uint32_t*)smem;       // [256][129] packed (hi,lo)

#pragma unroll
    for (int mt = 0; mt < 2; mt++)
#pragma unroll
        for (int half = 0; half < 2; half++) {
            int rloc = warpM + mt * 16 + half * 8 + qr;
            int row = row0 + rloc;
#pragma unroll
            for (int nt = 0; nt < 8; nt++) {
                int col = warpN + nt * 8 + qc;
                float v0 = acc[mt][nt][half * 2 + 0];
                float v1 = acc[mt][nt][half * 2 + 1];
                size_t idx = rmBase + (size_t)row * CC + col;
                if (hop >= 1) {
                    __nv_bfloat162 phv = *(const __nv_bfloat162*)(pH + idx);
                    __nv_bfloat162 plv = *(const __nv_bfloat162*)(pL + idx);
                    v0 = 2.f * v0 - (__bfloat162float(phv.x) + __bfloat162float(plv.x));
                    v1 = 2.f * v1 - (__bfloat162float(phv.y) + __bfloat162float(plv.y));
                }
                __nv_bfloat16 h0 = __float2bfloat16(v0);
                __nv_bfloat16 l0 = __float2bfloat16(v0 - __bfloat162float(h0));
                __nv_bfloat16 h1 = __float2bfloat16(v1);
                __nv_bfloat16 l1 = __float2bfloat16(v1 - __bfloat162float(h1));
                *(__nv_bfloat162*)(oH + idx) = __nv_bfloat162(h0, h1);
                *(__nv_bfloat162*)(oL + idx) = __nv_bfloat162(l0, l1);
                if (hop < 2) {
                    T[(uint32_t)col * 129 + rloc] =
                        (uint32_t)__bfloat16_as_ushort(h0) |
                        ((uint32_t)__bfloat16_as_ushort(l0) << 16);
                    T[(uint32_t)(col + 1) * 129 + rloc] =
                        (uint32_t)__bfloat16_as_ushort(h1) |
                        ((uint32_t)__bfloat16_as_ushort(l1) << 16);
                }
            }
        }

    if (hop < 2) {
        __syncthreads();
        __nv_bfloat16* tH = g_xth[hop + 1] + (size_t)b * CC * NN;
        __nv_bfloat16* tL = g_xtl[hop + 1] + (size_t)b * CC * NN;
#pragma unroll
        for (int i = 0; i < 32; i++) {
            int idx = tid + i * 512;
            int c = idx >> 6;
            int j = idx & 63;
            uint32_t p0 = T[(uint32_t)c * 129 + 2 * j];
            uint32_t p1 = T[(uint32_t)c * 129 + 2 * j + 1];
            size_t o = (size_t)c * NN + row0 + 2 * j;
            *(uint32_t*)(tH + o) = (p0 & 0xFFFFu) | ((p1 & 0xFFFFu) << 16);
            *(uint32_t*)(tL + o) = (p0 >> 16) | (p1 & 0xFFFF0000u);
        }
    }
}

// =================== HMMA gemm2 (1-sync pipeline) ========================
#define G2_STAGE 65536
#define G2_SMEM  (2 * G2_STAGE)

template<int MT>
__device__ __forceinline__ void hmma_stage(uint32_t st, uint32_t aLoOff,
                                           uint32_t bHiOff, uint32_t bLoOff,
                                           int warpM, int warpN, int lane,
                                           float (*acc)[8][4])
{
    const int arow = lane & 15;
    const int acol = (lane >> 4) << 4;
    const int g    = lane >> 3;
    const int brow = ((g >> 1) << 3) + (lane & 7);
    const int bcol = (g & 1) << 4;
#pragma unroll
    for (int ks = 0; ks < 4; ks++) {
        uint32_t ah[MT][4], al[MT][4];
#pragma unroll
        for (int mt = 0; mt < MT; mt++) {
            uint32_t off = SWZ((uint32_t)((warpM + mt * 16 + arow) * 128 + ks * 32 + acol));
            ldmx4(ah[mt], st + off);
            ldmx4(al[mt], st + aLoOff + off);
        }
#pragma unroll
        for (int np = 0; np < 4; np++) {
            uint32_t bh[4], bl[4];
            uint32_t off = SWZ((uint32_t)((warpN + np * 16 + brow) * 128 + ks * 32 + bcol));
            ldmx4(bh, st + bHiOff + off);
            ldmx4(bl, st + bLoOff + off);
#pragma unroll
            for (int mt = 0; mt < MT; mt++) {
                mma16816(acc[mt][np * 2],     ah[mt], &bh[0]);
                mma16816(acc[mt][np * 2],     ah[mt], &bl[0]);
                mma16816(acc[mt][np * 2],     al[mt], &bh[0]);
                mma16816(acc[mt][np * 2 + 1], ah[mt], &bh[2]);
                mma16816(acc[mt][np * 2 + 1], ah[mt], &bl[2]);
                mma16816(acc[mt][np * 2 + 1], al[mt], &bh[2]);
            }
        }
    }
}

__global__ __launch_bounds__(256, 1) void k_gemm2_mma(const float* __restrict__ gc_b)
{
    extern __shared__ char smem[];
    const uint32_t sb = smem_to_u32(smem);
    const int tid = threadIdx.x;
    const int wid = tid >> 5;
    const int lane = tid & 31;
    const int row0 = blockIdx.x * 128;
    const int warpM = (wid & 3) * 32;
    const int warpN = (wid >> 2) * 64;

    float acc[2][8][4];
#pragma unroll
    for (int i = 0; i < 2; i++)
#pragma unroll
        for (int j = 0; j < 8; j++)
#pragma unroll
            for (int q = 0; q < 4; q++) acc[i][j][q] = 0.f;

    auto load = [&](int s, int buf) {
        const int m  = s >> 2;
        const int c0 = (s & 3) * 64;
        const __nv_bfloat16* A_h = g_xrh[m] + (size_t)row0 * 256;
        const __nv_bfloat16* A_l = g_xrl[m] + (size_t)row0 * 256;
        const __nv_bfloat16* B_h = g_wth + m * 32768;
        const __nv_bfloat16* B_l = g_wtl + m * 32768;
        const uint32_t st = sb + buf * G2_STAGE;
#pragma unroll
        for (int i = 0; i < 4; i++) {
            int idx = tid + i * 256;
            int row = idx >> 3;
            int c16 = idx & 7;
            uint32_t off = SWZ((uint32_t)(row * 128 + c16 * 16));
            size_t src = (size_t)row * 256 + c0 + c16 * 8;
            CP16(st + off,         A_h + src);
            CP16(st + 16384 + off, A_l + src);
            CP16(st + 32768 + off, B_h + src);
            CP16(st + 49152 + off, B_l + src);
        }
        CP_COMMIT();
    };

    load(0, 0);
    for (int s = 0; s < 16; s++) {
        CP_WAIT0();
        __syncthreads();
        if (s + 1 < 16) load(s + 1, (s + 1) & 1);
        hmma_stage<2>(sb + (s & 1) * G2_STAGE, 16384, 32768, 49152,
                      warpM, warpN, lane, acc);
    }

    const int qr = lane >> 2;
    const int qc = (lane & 3) * 2;
#pragma unroll
    for (int mt = 0; mt < 2; mt++)
#pragma unroll
        for (int half = 0; half < 2; half++) {
            int row = row0 + warpM + mt * 16 + half * 8 + qr;
#pragma unroll
            for (int nt = 0; nt < 8; nt++) {
                int col = warpN + nt * 8 + qc;
                float v0 = acc[mt][nt][half * 2 + 0] + gc_b[col];
                float v1 = acc[mt][nt][half * 2 + 1] + gc_b[col + 1];
                v0 = (v0 >= 0.f) ? v0 : 0.01f * v0;
                v1 = (v1 >= 0.f) ? v1 : 0.01f * v1;
                *(float2*)(g_gco + (size_t)row * 128 + col) = make_float2(v0, v1);
            }
        }
}

// ---------------- sa[b,k] reduction ---------------------------------------
__global__ __launch_bounds__(256) void k_sa(const float* __restrict__ hidden,
                                            const float* __restrict__ att_w,
                                            const float* __restrict__ att_b)
{
    const int k = blockIdx.x;
    const int b = blockIdx.y;
    const float* hb = hidden + ((size_t)(b * 4 + k) << 17);
    const int tid = threadIdx.x;

    float sum = 0.f;
    for (int i = tid; i < NN * HIDD; i += 256) {
        int n = i >> 6, h = i & 63;
        float re = hb[(n << 7) + h];
        float im = hb[(n << 7) + 64 + h];
        float c = g_cos[(k << 16) + i];
        float s = g_sin[(k << 16) + i];
        sum += (c * re - s * im) * att_w[(n << 7) + h]
             + (s * re + c * im) * att_w[(n << 7) + 64 + h];
    }
    __shared__ float red[8];
    for (int o = 16; o; o >>= 1) sum += __shfl_down_sync(0xffffffffu, sum, o);
    if ((tid & 31) == 0) red[tid >> 5] = sum;
    __syncthreads();
    if (tid < 8) {
        float v = red[tid];
        for (int o = 4; o; o >>= 1) v += __shfl_down_sync(0xffu, v, o);
        if (tid == 0) g_sa[b * 4 + k] = v + att_b[0];
    }
}

__global__ void k_softmax()
{
    int b = threadIdx.x;
    if (b >= BSZ) return;
    float s0 = g_sa[b * 4 + 0], s1 = g_sa[b * 4 + 1];
    float s2 = g_sa[b * 4 + 2], s3 = g_sa[b * 4 + 3];
    float m = fmaxf(fmaxf(s0, s1), fmaxf(s2, s3));
    float e0 = expf(s0 - m), e1 = expf(s1 - m), e2 = expf(s2 - m), e3 = expf(s3 - m);
    float inv = 1.f / (e0 + e1 + e2 + e3);
    g_wa[b * 4 + 0] = e0 * inv;
    g_wa[b * 4 + 1] = e1 * inv;
    g_wa[b * 4 + 2] = e2 * inv;
    g_wa[b * 4 + 3] = e3 * inv;
}

// ---------------- final: out = gco@W + b + att (att fused inline) ---------
__global__ __launch_bounds__(256) void k_final(const float* __restrict__ W,
                                               const float* __restrict__ bias,
                                               const float* __restrict__ hidden,
                                               float* __restrict__ out)
{
    const int row0 = blockIdx.x * 64;
    __shared__ float As[16][68];
    __shared__ float Bs[16][132];
    const int tid = threadIdx.x;
    const int a_r = tid >> 2;
    const int a_c = (tid & 3) << 2;
    const int b_r = tid >> 5;
    const int b_c = (tid & 31) << 2;
    const int ty  = tid >> 4;
    const int tx  = tid & 15;

    float acc[4][8];
#pragma unroll
    for (int i = 0; i < 4; i++)
#pragma unroll
        for (int j = 0; j < 8; j++) acc[i][j] = 0.f;

    for (int k0 = 0; k0 < 128; k0 += 16) {
        float4 av = *(const float4*)(g_gco + (size_t)(row0 + a_r) * 128 + k0 + a_c);
        float4 b0 = *(const float4*)(W + (size_t)(k0 + b_r) * 128 + b_c);
        float4 b1 = *(const float4*)(W + (size_t)(k0 + b_r + 8) * 128 + b_c);
        __syncthreads();
        As[a_c + 0][a_r] = av.x; As[a_c + 1][a_r] = av.y;
        As[a_c + 2][a_r] = av.z; As[a_c + 3][a_r] = av.w;
        *(float4*)&Bs[b_r][b_c]     = b0;
        *(float4*)&Bs[b_r + 8][b_c] = b1;
        __syncthreads();
#pragma unroll
        for (int kk = 0; kk < 16; kk++) {
            float ar[4], br[8];
            *(float4*)&ar[0] = *(const float4*)&As[kk][ty * 4];
            *(float4*)&br[0] = *(const float4*)&Bs[kk][tx * 8];
            *(float4*)&br[4] = *(const float4*)&Bs[kk][tx * 8 + 4];
#pragma unroll
            for (int i = 0; i < 4; i++)
#pragma unroll
                for (int j = 0; j < 8; j++) acc[i][j] += ar[i] * br[j];
        }
    }

    const bool isIm = (tx >= 8);
#pragma unroll
    for (int i = 0; i < 4; i++) {
        int rr = row0 + ty * 4 + i;
        int b  = rr >> 10;
        int n  = rr & 1023;
        size_t nh_off = (size_t)OUT0 + (((size_t)(b * 4 + 3) << 10 | n) << 7);
        float was[4] = {g_wa[b * 4 + 0], g_wa[b * 4 + 1],
                        g_wa[b * 4 + 2], g_wa[b * 4 + 3]};
#pragma unroll
        for (int j = 0; j < 8; j++) {
            int col = tx * 8 + j;
            int h = col & 63;
            float att = 0.f;
#pragma unroll
            for (int k = 0; k < 4; k++) {
                const float* hb = hidden + ((size_t)(b * 4 + k) << 17);
                float re = hb[(n << 7) + h];
                float im = hb[(n << 7) + 64 + h];
                float c = g_cos[(k << 16) + (n << 6) + h];
                float s = g_sin[(k << 16) + (n << 6) + h];
                float v = isIm ? (s * re + c * im) : (c * re - s * im);
                att += was[k] * v;
            }
            float v = acc[i][j] + bias[(size_t)n * 128 + col] + att;
            out[(size_t)rr * 128 + col] = v;
            out[nh_off + col]           = v;
        }
    }
}

__global__ __launch_bounds__(256) void k_copy(const float* __restrict__ hidden,
                                              float* __restrict__ out)
{
    int i4 = blockIdx.x * 256 + threadIdx.x;
    const int per_b = 3 * (NN * DD) / 4;
    if (i4 >= BSZ * per_b) return;
    int b  = i4 / per_b;
    int r4 = i4 - b * per_b;
    const float4* hv = (const float4*)hidden;
    float4* ov = (float4*)out;
    ov[(OUT0 / 4) + (size_t)b * 131072 + r4] = hv[(size_t)b * 131072 + 32768 + r4];
}

// ---------------- launch ---------------------------------------------------
extern "C" void kernel_launch(void* const* d_in, const int* in_sizes, int n_in,
                              void* d_out, int out_size)
{
    const float* inputs   = (const float*)d_in[0];
    const float* supports = (const float*)d_in[1];
    const float* hidden   = (const float*)d_in[2];
    const float* W        = (const float*)d_in[3];
    const float* bias     = (const float*)d_in[4];
    const float* R        = (const float*)d_in[5];
    const float* gc_w  = (const float*)d_in[6];
    const float* gc_b  = (const float*)d_in[7];
    const float* att_w = (const float*)d_in[10];
    const float* att_b = (const float*)d_in[11];
    float* out = (float*)d_out;

    static bool attrs_set = false;
    if (!attrs_set) {
        cudaFuncSetAttribute(k_cheb_mma, cudaFuncAttributeMaxDynamicSharedMemorySize, CB_SMEM);
        cudaFuncSetAttribute(k_gemm2_mma, cudaFuncAttributeMaxDynamicSharedMemorySize, G2_SMEM);
        attrs_set = true;
    }

    // order keeps cheb at capture position
    k_sconv<<<(BSZ * NN * NN / 4 + 255) / 256, 256>>>(supports);
    k_build_x0<<<dim3(NN / 32, CC / 32, BSZ), 256>>>(inputs, hidden);

    dim3 gC(8, BSZ);
    k_cheb_mma<<<gC, 512, CB_SMEM>>>(0);
    k_cheb_mma<<<gC, 512, CB_SMEM>>>(1);
    k_cheb_mma<<<gC, 512, CB_SMEM>>>(2);

    k_wt<<<(4 * 128 * 256 + 255) / 256, 256>>>(gc_w);
    k_cs<<<(PREK * NN * HIDD + 255) / 256, 256>>>(R);

    k_gemm2_mma<<<128, 256, G2_SMEM>>>(gc_b);

    k_sa<<<dim3(PREK, BSZ), 256>>>(hidden, att_w, att_b);
    k_softmax<<<1, 32>>>();

    k_final<<<(BSZ * NN) / 64, 256>>>(W, bias, hidden, out);
    k_copy<<<(BSZ * 3 * NN * DD / 4 + 255) / 256, 256>>>(hidden, out);
}

// round 7
// speedup vs baseline: 2.3738x; 1.1732x over previous
#include <cuda_runtime.h>
#include <cuda_fp16.h>
#include <cstdint>

#define BSZ   16
#define NN    1024
#define HIDD  64
#define DD    128
#define CC    256
#define PREK  4

#define XSZ   (BSZ * NN * CC)
#define OUT0  (BSZ * NN * DD)

#define PHASE_SCALE ((float)(3.141592653589793 / 0.21875))

// ===================== base-ISA tensor helpers (sm_80+) =====================
__device__ __forceinline__ uint32_t smem_to_u32(const void* p) {
    uint32_t a;
    asm("{ .reg .u64 t; cvta.to.shared.u64 t, %1; cvt.u32.u64 %0, t; }" : "=r"(a) : "l"(p));
    return a;
}
__device__ __forceinline__ void ldmx4(uint32_t* r, uint32_t addr) {
    asm volatile("ldmatrix.sync.aligned.m8n8.x4.shared.b16 {%0,%1,%2,%3}, [%4];"
        : "=r"(r[0]), "=r"(r[1]), "=r"(r[2]), "=r"(r[3]) : "r"(addr));
}
__device__ __forceinline__ void mma16816(float* c, const uint32_t* a, const uint32_t* b) {
    asm volatile("mma.sync.aligned.m16n8k16.row.col.f32.f16.f16.f32 "
        "{%0,%1,%2,%3}, {%4,%5,%6,%7}, {%8,%9}, {%0,%1,%2,%3};"
        : "+f"(c[0]), "+f"(c[1]), "+f"(c[2]), "+f"(c[3])
        : "r"(a[0]), "r"(a[1]), "r"(a[2]), "r"(a[3]), "r"(b[0]), "r"(b[1]));
}
#define CP16(dst, src) \
    asm volatile("cp.async.cg.shared.global [%0], [%1], 16;" :: "r"(dst), "l"(src))
#define CP_COMMIT() asm volatile("cp.async.commit_group;" ::: "memory")
#define CP_WAIT0()  asm volatile("cp.async.wait_group 0;" ::: "memory")
#define SWZ(off) ((off) ^ (((off) >> 3) & 0x70))

// ========================= scratch =========================
__device__ __align__(16) __half g_sh[BSZ * NN * NN];      // supports fp16 (single)
__device__ __align__(16) __half g_xth[3][BSZ * CC * NN];  // x^T hi [c][n]
__device__ __align__(16) __half g_xtl[3][BSZ * CC * NN];  // x^T lo
__device__ __align__(16) __half g_xrh[4][XSZ];            // x row-major hi
__device__ __align__(16) __half g_xrl[4][XSZ];            // x row-major lo
__device__ __align__(16) __half g_wt[4 * 128 * 256];      // gc_w^T fp16 (single)
__device__ float g_gco[BSZ * NN * DD];
__device__ float g_cos[PREK * NN * HIDD];
__device__ float g_sin[PREK * NN * HIDD];
__device__ float g_sa[BSZ * PREK];
__device__ float g_wa[BSZ * PREK];

// ---------------- S -> fp16 ---------------------------------------------
__global__ __launch_bounds__(256) void k_sconv(const float* __restrict__ S)
{
    int i = blockIdx.x * 256 + threadIdx.x;
    const int total = BSZ * NN * NN / 4;
    if (i >= total) return;
    float4 v = ((const float4*)S)[i];
    __half2* ph = (__half2*)g_sh;
    ph[i * 2]     = __half2(__float2half(v.x), __float2half(v.y));
    ph[i * 2 + 1] = __half2(__float2half(v.z), __float2half(v.w));
}

// ---------------- build x0: row-major hi/lo + transposed hi/lo ----------
__global__ __launch_bounds__(256) void k_build_x0(const float* __restrict__ inputs,
                                                  const float* __restrict__ hidden)
{
    __shared__ float tile[32][33];
    const int n0 = blockIdx.x * 32;
    const int c0 = blockIdx.y * 32;
    const int b  = blockIdx.z;
    const int lane = threadIdx.x & 31;
    const int wrp  = threadIdx.x >> 5;

#pragma unroll
    for (int r = 0; r < 4; r++) {
        int nl = wrp * 4 + r;
        int n = n0 + nl;
        int c = c0 + lane;
        float v;
        if (c < 64)        v = inputs[((size_t)(b * NN + n)) * 128 + c];
        else if (c < 128)  v = hidden[(((size_t)(b * 4 + 3) * NN + n)) * 128 + (c - 64)];
        else if (c < 192)  v = inputs[((size_t)(b * NN + n)) * 128 + (c - 128 + 64)];
        else               v = hidden[(((size_t)(b * 4 + 3) * NN + n)) * 128 + (c - 192 + 64)];
        __half h = __float2half(v);
        __half l = __float2half(v - __half2float(h));
        size_t o = ((size_t)(b * NN + n)) * CC + c;
        g_xrh[0][o] = h;
        g_xrl[0][o] = l;
        tile[nl][lane] = v;
    }
    __syncthreads();
#pragma unroll
    for (int r = 0; r < 4; r++) {
        int cl = wrp * 4 + r;
        float v = tile[lane][cl];
        __half h = __float2half(v);
        __half l = __float2half(v - __half2float(h));
        size_t o = ((size_t)b * CC + c0 + cl) * NN + n0 + lane;
        g_xth[0][o] = h;
        g_xtl[0][o] = l;
    }
}

// ---------------- gc_w -> wt fp16 [m][d][c] ------------------------------
__global__ __launch_bounds__(256) void k_wt(const float* __restrict__ gc_w)
{
    int i = blockIdx.x * 256 + threadIdx.x;
    if (i >= 4 * 128 * 256) return;
    int c = i & 255;
    int d = (i >> 8) & 127;
    int m = i >> 15;
    g_wt[i] = __float2half(gc_w[(size_t)d * 1024 + c * 4 + m]);
}

// ---------------- cos/sin tables ----------------------------------------
__global__ __launch_bounds__(256) void k_cs(const float* __restrict__ R)
{
    int i = blockIdx.x * 256 + threadIdx.x;
    if (i >= PREK * NN * HIDD) return;
    float ph = R[i] * PHASE_SCALE;
    float s, c;
    sincosf(ph, &s, &c);
    g_cos[i] = c;
    g_sin[i] = s;
}

// =================== fp16 HMMA Chebyshev GEMM ============================
// stage: A 16K | Bh 32K | Bl 32K = 80K; x2 = 160K.
#define CB_STAGE 81920
#define CB_SMEM  (2 * CB_STAGE)

__device__ __forceinline__ void cheb_load512(uint32_t sb, int buf, int tid,
    const __half* A, const __half* B_h, const __half* B_l, int k0)
{
    const uint32_t st = sb + buf * CB_STAGE;
#pragma unroll
    for (int i = 0; i < 2; i++) {                    // A: 128 rows
        int idx = tid + i * 512;
        int row = idx >> 3;
        int c16 = idx & 7;
        uint32_t off = SWZ((uint32_t)(row * 128 + c16 * 16));
        size_t src = (size_t)row * 1024 + k0 + c16 * 8;
        CP16(st + off, A + src);
    }
#pragma unroll
    for (int i = 0; i < 4; i++) {                    // B: 256 rows
        int idx = tid + i * 512;
        int row = idx >> 3;
        int c16 = idx & 7;
        uint32_t off = SWZ((uint32_t)(row * 128 + c16 * 16));
        size_t src = (size_t)row * 1024 + k0 + c16 * 8;
        CP16(st + 16384 + off, B_h + src);
        CP16(st + 49152 + off, B_l + src);
    }
    CP_COMMIT();
}

__device__ __forceinline__ void hmma_stage512(uint32_t st, int warpM, int warpN,
                                              int lane, float acc[2][8][4])
{
    const int arow = lane & 15;
    const int acol = (lane >> 4) << 4;
    const int g    = lane >> 3;
    const int brow = ((g >> 1) << 3) + (lane & 7);
    const int bcol = (g & 1) << 4;
#pragma unroll
    for (int ks = 0; ks < 4; ks++) {
        uint32_t a[2][4];
#pragma unroll
        for (int mt = 0; mt < 2; mt++) {
            uint32_t off = SWZ((uint32_t)((warpM + mt * 16 + arow) * 128 + ks * 32 + acol));
            ldmx4(a[mt], st + off);
        }
#pragma unroll
        for (int np = 0; np < 4; np++) {
            uint32_t bh[4], bl[4];
            uint32_t off = SWZ((uint32_t)((warpN + np * 16 + brow) * 128 + ks * 32 + bcol));
            ldmx4(bh, st + 16384 + off);
            ldmx4(bl, st + 49152 + off);
#pragma unroll
            for (int mt = 0; mt < 2; mt++) {
                mma16816(acc[mt][np * 2],     a[mt], &bh[0]);
                mma16816(acc[mt][np * 2],     a[mt], &bl[0]);
                mma16816(acc[mt][np * 2 + 1], a[mt], &bh[2]);
                mma16816(acc[mt][np * 2 + 1], a[mt], &bl[2]);
            }
        }
    }
}

__global__ __launch_bounds__(512, 1) void k_cheb_mma(int hop)
{
    extern __shared__ char smem[];
    const uint32_t sb = smem_to_u32(smem);
    const int tid = threadIdx.x;
    const int wid = tid >> 5;
    const int lane = tid & 31;
    const int row0 = blockIdx.x * 128;
    const int b = blockIdx.y;
    const int warpM = (wid & 3) * 32;
    const int warpN = (wid >> 2) * 64;

    const __half* A   = g_sh + ((size_t)b * NN + row0) * NN;
    const __half* B_h = g_xth[hop] + (size_t)b * CC * NN;
    const __half* B_l = g_xtl[hop] + (size_t)b * CC * NN;

    float acc[2][8][4];
#pragma unroll
    for (int i = 0; i < 2; i++)
#pragma unroll
        for (int j = 0; j < 8; j++)
#pragma unroll
            for (int q = 0; q < 4; q++) acc[i][j][q] = 0.f;

    cheb_load512(sb, 0, tid, A, B_h, B_l, 0);

    for (int s = 0; s < 16; s++) {
        CP_WAIT0();
        __syncthreads();
        if (s + 1 < 16)
            cheb_load512(sb, (s + 1) & 1, tid, A, B_h, B_l, (s + 1) * 64);
        hmma_stage512(sb + (s & 1) * CB_STAGE, warpM, warpN, lane, acc);
    }
    __syncthreads();   // protect smem reuse (transpose buffer)

    // ---------------- epilogue ----------------
    const int qr = lane >> 2;
    const int qc = (lane & 3) * 2;
    const size_t rmBase = (size_t)b * NN * CC;
    const __half* pH = (hop >= 1) ? g_xrh[hop - 1] : nullptr;
    const __half* pL = (hop >= 1) ? g_xrl[hop - 1] : nullptr;
    __half* oH = g_xrh[hop + 1];
    __half* oL = g_xrl[hop + 1];

    uint32_t* T = (uint32_t*)smem;       // [256][129] packed (hi,lo)

#pragma unroll
    for (int mt = 0; mt < 2; mt++)
#pragma unroll
        for (int half_ = 0; half_ < 2; half_++) {
            int rloc = warpM + mt * 16 + half_ * 8 + qr;
            int row = row0 + rloc;
#pragma unroll
            for (int nt = 0; nt < 8; nt++) {
                int col = warpN + nt * 8 + qc;
                float v0 = acc[mt][nt][half_ * 2 + 0];
                float v1 = acc[mt][nt][half_ * 2 + 1];
                size_t idx = rmBase + (size_t)row * CC + col;
                if (hop >= 1) {
                    __half2 phv = *(const __half2*)(pH + idx);
                    __half2 plv = *(const __half2*)(pL + idx);
                    v0 = 2.f * v0 - (__half2float(phv.x) + __half2float(plv.x));
                    v1 = 2.f * v1 - (__half2float(phv.y) + __half2float(plv.y));
                }
                __half h0 = __float2half(v0);
                __half l0 = __float2half(v0 - __half2float(h0));
                __half h1 = __float2half(v1);
                __half l1 = __float2half(v1 - __half2float(h1));
                *(__half2*)(oH + idx) = __half2(h0, h1);
                *(__half2*)(oL + idx) = __half2(l0, l1);
                if (hop < 2) {
                    T[(uint32_t)col * 129 + rloc] =
                        (uint32_t)__half_as_ushort(h0) |
                        ((uint32_t)__half_as_ushort(l0) << 16);
                    T[(uint32_t)(col + 1) * 129 + rloc] =
                        (uint32_t)__half_as_ushort(h1) |
                        ((uint32_t)__half_as_ushort(l1) << 16);
                }
            }
        }

    if (hop < 2) {
        __syncthreads();
        __half* tH = g_xth[hop + 1] + (size_t)b * CC * NN;
        __half* tL = g_xtl[hop + 1] + (size_t)b * CC * NN;
#pragma unroll
        for (int i = 0; i < 32; i++) {
            int idx = tid + i * 512;
            int c = idx >> 6;
            int j = idx & 63;
            uint32_t p0 = T[(uint32_t)c * 129 + 2 * j];
            uint32_t p1 = T[(uint32_t)c * 129 + 2 * j + 1];
            size_t o = (size_t)c * NN + row0 + 2 * j;
            *(uint32_t*)(tH + o) = (p0 & 0xFFFFu) | ((p1 & 0xFFFFu) << 16);
            *(uint32_t*)(tL + o) = (p0 >> 16) | (p1 & 0xFFFF0000u);
        }
    }
}

// =================== fp16 HMMA gemm2 =====================================
// stage: Ah 16K | Al 16K | B 16K = 48K; x2 = 96K.
#define G2_STAGE 49152
#define G2_SMEM  (2 * G2_STAGE)

__global__ __launch_bounds__(256, 1) void k_gemm2_mma(const float* __restrict__ gc_b)
{
    extern __shared__ char smem[];
    const uint32_t sb = smem_to_u32(smem);
    const int tid = threadIdx.x;
    const int wid = tid >> 5;
    const int lane = tid & 31;
    const int row0 = blockIdx.x * 128;
    const int warpM = (wid & 3) * 32;
    const int warpN = (wid >> 2) * 64;

    float acc[2][8][4];
#pragma unroll
    for (int i = 0; i < 2; i++)
#pragma unroll
        for (int j = 0; j < 8; j++)
#pragma unroll
            for (int q = 0; q < 4; q++) acc[i][j][q] = 0.f;

    auto load = [&](int s, int buf) {
        const int m  = s >> 2;
        const int c0 = (s & 3) * 64;
        const __half* A_h = g_xrh[m] + (size_t)row0 * 256;
        const __half* A_l = g_xrl[m] + (size_t)row0 * 256;
        const __half* B   = g_wt + m * 32768;
        const uint32_t st = sb + buf * G2_STAGE;
#pragma unroll
        for (int i = 0; i < 4; i++) {
            int idx = tid + i * 256;
            int row = idx >> 3;
            int c16 = idx & 7;
            uint32_t off = SWZ((uint32_t)(row * 128 + c16 * 16));
            size_t src = (size_t)row * 256 + c0 + c16 * 8;
            CP16(st + off,         A_h + src);
            CP16(st + 16384 + off, A_l + src);
            CP16(st + 32768 + off, B + src);
        }
        CP_COMMIT();
    };

    const int arow = lane & 15;
    const int acol = (lane >> 4) << 4;
    const int g    = lane >> 3;
    const int brow = ((g >> 1) << 3) + (lane & 7);
    const int bcol = (g & 1) << 4;

    load(0, 0);
    for (int s = 0; s < 16; s++) {
        CP_WAIT0();
        __syncthreads();
        if (s + 1 < 16) load(s + 1, (s + 1) & 1);
        const uint32_t st = sb + (s & 1) * G2_STAGE;
#pragma unroll
        for (int ks = 0; ks < 4; ks++) {
            uint32_t ah[2][4], al[2][4];
#pragma unroll
            for (int mt = 0; mt < 2; mt++) {
                uint32_t off = SWZ((uint32_t)((warpM + mt * 16 + arow) * 128 + ks * 32 + acol));
                ldmx4(ah[mt], st + off);
                ldmx4(al[mt], st + 16384 + off);
            }
#pragma unroll
            for (int np = 0; np < 4; np++) {
                uint32_t bf[4];
                uint32_t off = SWZ((uint32_t)((warpN + np * 16 + brow) * 128 + ks * 32 + bcol));
                ldmx4(bf, st + 32768 + off);
#pragma unroll
                for (int mt = 0; mt < 2; mt++) {
                    mma16816(acc[mt][np * 2],     ah[mt], &bf[0]);
                    mma16816(acc[mt][np * 2],     al[mt], &bf[0]);
                    mma16816(acc[mt][np * 2 + 1], ah[mt], &bf[2]);
                    mma16816(acc[mt][np * 2 + 1], al[mt], &bf[2]);
                }
            }
        }
    }

    const int qr = lane >> 2;
    const int qc = (lane & 3) * 2;
#pragma unroll
    for (int mt = 0; mt < 2; mt++)
#pragma unroll
        for (int half_ = 0; half_ < 2; half_++) {
            int row = row0 + warpM + mt * 16 + half_ * 8 + qr;
#pragma unroll
            for (int nt = 0; nt < 8; nt++) {
                int col = warpN + nt * 8 + qc;
                float v0 = acc[mt][nt][half_ * 2 + 0] + gc_b[col];
                float v1 = acc[mt][nt][half_ * 2 + 1] + gc_b[col + 1];
                v0 = (v0 >= 0.f) ? v0 : 0.01f * v0;
                v1 = (v1 >= 0.f) ? v1 : 0.01f * v1;
                *(float2*)(g_gco + (size_t)row * 128 + col) = make_float2(v0, v1);
            }
        }
}

// ---------------- sa[b,k] reduction ---------------------------------------
__global__ __launch_bounds__(256) void k_sa(const float* __restrict__ hidden,
                                            const float* __restrict__ att_w,
                                            const float* __restrict__ att_b)
{
    const int k = blockIdx.x;
    const int b = blockIdx.y;
    const float* hb = hidden + ((size_t)(b * 4 + k) << 17);
    const int tid = threadIdx.x;

    float sum = 0.f;
    for (int i = tid; i < NN * HIDD; i += 256) {
        int n = i >> 6, h = i & 63;
        float re = hb[(n << 7) + h];
        float im = hb[(n << 7) + 64 + h];
        float c = g_cos[(k << 16) + i];
        float s = g_sin[(k << 16) + i];
        sum += (c * re - s * im) * att_w[(n << 7) + h]
             + (s * re + c * im) * att_w[(n << 7) + 64 + h];
    }
    __shared__ float red[8];
    for (int o = 16; o; o >>= 1) sum += __shfl_down_sync(0xffffffffu, sum, o);
    if ((tid & 31) == 0) red[tid >> 5] = sum;
    __syncthreads();
    if (tid < 8) {
        float v = red[tid];
        for (int o = 4; o; o >>= 1) v += __shfl_down_sync(0xffu, v, o);
        if (tid == 0) g_sa[b * 4 + k] = v + att_b[0];
    }
}

__global__ void k_softmax()
{
    int b = threadIdx.x;
    if (b >= BSZ) return;
    float s0 = g_sa[b * 4 + 0], s1 = g_sa[b * 4 + 1];
    float s2 = g_sa[b * 4 + 2], s3 = g_sa[b * 4 + 3];
    float m = fmaxf(fmaxf(s0, s1), fmaxf(s2, s3));
    float e0 = expf(s0 - m), e1 = expf(s1 - m), e2 = expf(s2 - m), e3 = expf(s3 - m);
    float inv = 1.f / (e0 + e1 + e2 + e3);
    g_wa[b * 4 + 0] = e0 * inv;
    g_wa[b * 4 + 1] = e1 * inv;
    g_wa[b * 4 + 2] = e2 * inv;
    g_wa[b * 4 + 3] = e3 * inv;
}

// ---------------- final: out = gco@W + b + att (att fused inline) ---------
__global__ __launch_bounds__(256) void k_final(const float* __restrict__ W,
                                               const float* __restrict__ bias,
                                               const float* __restrict__ hidden,
                                               float* __restrict__ out)
{
    const int row0 = blockIdx.x * 64;
    __shared__ float As[16][68];
    __shared__ float Bs[16][132];
    const int tid = threadIdx.x;
    const int a_r = tid >> 2;
    const int a_c = (tid & 3) << 2;
    const int b_r = tid >> 5;
    const int b_c = (tid & 31) << 2;
    const int ty  = tid >> 4;
    const int tx  = tid & 15;

    float acc[4][8];
#pragma unroll
    for (int i = 0; i < 4; i++)
#pragma unroll
        for (int j = 0; j < 8; j++) acc[i][j] = 0.f;

    for (int k0 = 0; k0 < 128; k0 += 16) {
        float4 av = *(const float4*)(g_gco + (size_t)(row0 + a_r) * 128 + k0 + a_c);
        float4 b0 = *(const float4*)(W + (size_t)(k0 + b_r) * 128 + b_c);
        float4 b1 = *(const float4*)(W + (size_t)(k0 + b_r + 8) * 128 + b_c);
        __syncthreads();
        As[a_c + 0][a_r] = av.x; As[a_c + 1][a_r] = av.y;
        As[a_c + 2][a_r] = av.z; As[a_c + 3][a_r] = av.w;
        *(float4*)&Bs[b_r][b_c]     = b0;
        *(float4*)&Bs[b_r + 8][b_c] = b1;
        __syncthreads();
#pragma unroll
        for (int kk = 0; kk < 16; kk++) {
            float ar[4], br[8];
            *(float4*)&ar[0] = *(const float4*)&As[kk][ty * 4];
            *(float4*)&br[0] = *(const float4*)&Bs[kk][tx * 8];
            *(float4*)&br[4] = *(const float4*)&Bs[kk][tx * 8 + 4];
#pragma unroll
            for (int i = 0; i < 4; i++)
#pragma unroll
                for (int j = 0; j < 8; j++) acc[i][j] += ar[i] * br[j];
        }
    }

    const bool isIm = (tx >= 8);
#pragma unroll
    for (int i = 0; i < 4; i++) {
        int rr = row0 + ty * 4 + i;
        int b  = rr >> 10;
        int n  = rr & 1023;
        size_t nh_off = (size_t)OUT0 + (((size_t)(b * 4 + 3) << 10 | n) << 7);
        float was[4] = {g_wa[b * 4 + 0], g_wa[b * 4 + 1],
                        g_wa[b * 4 + 2], g_wa[b * 4 + 3]};
#pragma unroll
        for (int j = 0; j < 8; j++) {
            int col = tx * 8 + j;
            int h = col & 63;
            float att = 0.f;
#pragma unroll
            for (int k = 0; k < 4; k++) {
                const float* hb = hidden + ((size_t)(b * 4 + k) << 17);
                float re = hb[(n << 7) + h];
                float im = hb[(n << 7) + 64 + h];
                float c = g_cos[(k << 16) + (n << 6) + h];
                float s = g_sin[(k << 16) + (n << 6) + h];
                float v = isIm ? (s * re + c * im) : (c * re - s * im);
                att += was[k] * v;
            }
            float v = acc[i][j] + bias[(size_t)n * 128 + col] + att;
            out[(size_t)rr * 128 + col] = v;
            out[nh_off + col]           = v;
        }
    }
}

__global__ __launch_bounds__(256) void k_copy(const float* __restrict__ hidden,
                                              float* __restrict__ out)
{
    int i4 = blockIdx.x * 256 + threadIdx.x;
    const int per_b = 3 * (NN * DD) / 4;
    if (i4 >= BSZ * per_b) return;
    int b  = i4 / per_b;
    int r4 = i4 - b * per_b;
    const float4* hv = (const float4*)hidden;
    float4* ov = (float4*)out;
    ov[(OUT0 / 4) + (size_t)b * 131072 + r4] = hv[(size_t)b * 131072 + 32768 + r4];
}

// ---------------- launch ---------------------------------------------------
extern "C" void kernel_launch(void* const* d_in, const int* in_sizes, int n_in,
                              void* d_out, int out_size)
{
    const float* inputs   = (const float*)d_in[0];
    const float* supports = (const float*)d_in[1];
    const float* hidden   = (const float*)d_in[2];
    const float* W        = (const float*)d_in[3];
    const float* bias     = (const float*)d_in[4];
    const float* R        = (const float*)d_in[5];
    const float* gc_w  = (const float*)d_in[6];
    const float* gc_b  = (const float*)d_in[7];
    const float* att_w = (const float*)d_in[10];
    const float* att_b = (const float*)d_in[11];
    float* out = (float*)d_out;

    static bool attrs_set = false;
    if (!attrs_set) {
        cudaFuncSetAttribute(k_cheb_mma, cudaFuncAttributeMaxDynamicSharedMemorySize, CB_SMEM);
        cudaFuncSetAttribute(k_gemm2_mma, cudaFuncAttributeMaxDynamicSharedMemorySize, G2_SMEM);
        attrs_set = true;
    }

    k_sconv<<<(BSZ * NN * NN / 4 + 255) / 256, 256>>>(supports);
    k_build_x0<<<dim3(NN / 32, CC / 32, BSZ), 256>>>(inputs, hidden);

    dim3 gC(8, BSZ);
    k_cheb_mma<<<gC, 512, CB_SMEM>>>(0);
    k_cheb_mma<<<gC, 512, CB_SMEM>>>(1);
    k_cheb_mma<<<gC, 512, CB_SMEM>>>(2);

    k_wt<<<(4 * 128 * 256 + 255) / 256, 256>>>(gc_w);
    k_cs<<<(PREK * NN * HIDD + 255) / 256, 256>>>(R);

    k_gemm2_mma<<<128, 256, G2_SMEM>>>(gc_b);

    k_sa<<<dim3(PREK, BSZ), 256>>>(hidden, att_w, att_b);
    k_softmax<<<1, 32>>>();

    k_final<<<(BSZ * NN) / 64, 256>>>(W, bias, hidden, out);
    k_copy<<<(BSZ * 3 * NN * DD / 4 + 255) / 256, 256>>>(hidden, out);
}

// round 8
// speedup vs baseline: 2.8859x; 1.2157x over previous
#include <cuda_runtime.h>
#include <cuda_fp16.h>
#include <cstdint>

#define BSZ   16
#define NN    1024
#define HIDD  64
#define DD    128
#define CC    256
#define PREK  4

#define XSZ   (BSZ * NN * CC)
#define OUT0  (BSZ * NN * DD)

#define PHASE_SCALE ((float)(3.141592653589793 / 0.21875))

// ===================== base-ISA tensor helpers (sm_80+) =====================
__device__ __forceinline__ uint32_t smem_to_u32(const void* p) {
    uint32_t a;
    asm("{ .reg .u64 t; cvta.to.shared.u64 t, %1; cvt.u32.u64 %0, t; }" : "=r"(a) : "l"(p));
    return a;
}
__device__ __forceinline__ void ldmx4(uint32_t* r, uint32_t addr) {
    asm volatile("ldmatrix.sync.aligned.m8n8.x4.shared.b16 {%0,%1,%2,%3}, [%4];"
        : "=r"(r[0]), "=r"(r[1]), "=r"(r[2]), "=r"(r[3]) : "r"(addr));
}
__device__ __forceinline__ void mma16816(float* c, const uint32_t* a, const uint32_t* b) {
    asm volatile("mma.sync.aligned.m16n8k16.row.col.f32.f16.f16.f32 "
        "{%0,%1,%2,%3}, {%4,%5,%6,%7}, {%8,%9}, {%0,%1,%2,%3};"
        : "+f"(c[0]), "+f"(c[1]), "+f"(c[2]), "+f"(c[3])
        : "r"(a[0]), "r"(a[1]), "r"(a[2]), "r"(a[3]), "r"(b[0]), "r"(b[1]));
}
#define CP16(dst, src) \
    asm volatile("cp.async.cg.shared.global [%0], [%1], 16;" :: "r"(dst), "l"(src))
#define CP_COMMIT() asm volatile("cp.async.commit_group;" ::: "memory")
#define CP_WAIT0()  asm volatile("cp.async.wait_group 0;" ::: "memory")
#define SWZ(off) ((off) ^ (((off) >> 3) & 0x70))

// ========================= scratch =========================
__device__ __align__(16) __half g_sh[BSZ * NN * NN];      // supports fp16
__device__ __align__(16) __half g_xth[3][BSZ * CC * NN];  // x^T hi (MMA B operand)
__device__ __align__(16) __half g_xrh[4][XSZ];            // x row-major hi
__device__ __align__(16) __half g_xrl[4][XSZ];            // x row-major lo (recurrence state)
__device__ __align__(16) __half g_wt[4 * 128 * 256];      // gc_w^T fp16
__device__ float g_gco[BSZ * NN * DD];
__device__ float g_cos[PREK * NN * HIDD];
__device__ float g_sin[PREK * NN * HIDD];
__device__ float g_sa[BSZ * PREK];
__device__ float g_wa[BSZ * PREK];

// ---------------- S -> fp16 ---------------------------------------------
__global__ __launch_bounds__(256) void k_sconv(const float* __restrict__ S)
{
    int i = blockIdx.x * 256 + threadIdx.x;
    const int total = BSZ * NN * NN / 4;
    if (i >= total) return;
    float4 v = ((const float4*)S)[i];
    __half2* ph = (__half2*)g_sh;
    ph[i * 2]     = __half2(__float2half(v.x), __float2half(v.y));
    ph[i * 2 + 1] = __half2(__float2half(v.z), __float2half(v.w));
}

// ---------------- build x0 ------------------------------------------------
__global__ __launch_bounds__(256) void k_build_x0(const float* __restrict__ inputs,
                                                  const float* __restrict__ hidden)
{
    __shared__ float tile[32][33];
    const int n0 = blockIdx.x * 32;
    const int c0 = blockIdx.y * 32;
    const int b  = blockIdx.z;
    const int lane = threadIdx.x & 31;
    const int wrp  = threadIdx.x >> 5;

#pragma unroll
    for (int r = 0; r < 4; r++) {
        int nl = wrp * 4 + r;
        int n = n0 + nl;
        int c = c0 + lane;
        float v;
        if (c < 64)        v = inputs[((size_t)(b * NN + n)) * 128 + c];
        else if (c < 128)  v = hidden[(((size_t)(b * 4 + 3) * NN + n)) * 128 + (c - 64)];
        else if (c < 192)  v = inputs[((size_t)(b * NN + n)) * 128 + (c - 128 + 64)];
        else               v = hidden[(((size_t)(b * 4 + 3) * NN + n)) * 128 + (c - 192 + 64)];
        __half h = __float2half(v);
        __half l = __float2half(v - __half2float(h));
        size_t o = ((size_t)(b * NN + n)) * CC + c;
        g_xrh[0][o] = h;
        g_xrl[0][o] = l;
        tile[nl][lane] = v;
    }
    __syncthreads();
#pragma unroll
    for (int r = 0; r < 4; r++) {
        int cl = wrp * 4 + r;
        float v = tile[lane][cl];
        size_t o = ((size_t)b * CC + c0 + cl) * NN + n0 + lane;
        g_xth[0][o] = __float2half(v);
    }
}

// ---------------- gc_w -> wt fp16 [m][d][c] ------------------------------
__global__ __launch_bounds__(256) void k_wt(const float* __restrict__ gc_w)
{
    int i = blockIdx.x * 256 + threadIdx.x;
    if (i >= 4 * 128 * 256) return;
    int c = i & 255;
    int d = (i >> 8) & 127;
    int m = i >> 15;
    g_wt[i] = __float2half(gc_w[(size_t)d * 1024 + c * 4 + m]);
}

// ---------------- cos/sin tables ----------------------------------------
__global__ __launch_bounds__(256) void k_cs(const float* __restrict__ R)
{
    int i = blockIdx.x * 256 + threadIdx.x;
    if (i >= PREK * NN * HIDD) return;
    float ph = R[i] * PHASE_SCALE;
    float s, c;
    sincosf(ph, &s, &c);
    g_cos[i] = c;
    g_sin[i] = s;
}

// =================== fp16 1-MMA Chebyshev GEMM ===========================
// stage: A 16K | B 32K = 48K; x2 = 96K. Transpose buffer 256x130 ushort = 65KB.
#define CB_STAGE 49152
#define CB_SMEM  (2 * CB_STAGE)

__device__ __forceinline__ void cheb_load512(uint32_t sb, int buf, int tid,
    const __half* A, const __half* B, int k0)
{
    const uint32_t st = sb + buf * CB_STAGE;
#pragma unroll
    for (int i = 0; i < 2; i++) {                    // A: 128 rows
        int idx = tid + i * 512;
        int row = idx >> 3;
        int c16 = idx & 7;
        uint32_t off = SWZ((uint32_t)(row * 128 + c16 * 16));
        CP16(st + off, A + (size_t)row * 1024 + k0 + c16 * 8);
    }
#pragma unroll
    for (int i = 0; i < 4; i++) {                    // B: 256 rows
        int idx = tid + i * 512;
        int row = idx >> 3;
        int c16 = idx & 7;
        uint32_t off = SWZ((uint32_t)(row * 128 + c16 * 16));
        CP16(st + 16384 + off, B + (size_t)row * 1024 + k0 + c16 * 8);
    }
    CP_COMMIT();
}

__device__ __forceinline__ void hmma_stage512(uint32_t st, int warpM, int warpN,
                                              int lane, float acc[2][8][4])
{
    const int arow = lane & 15;
    const int acol = (lane >> 4) << 4;
    const int g    = lane >> 3;
    const int brow = ((g >> 1) << 3) + (lane & 7);
    const int bcol = (g & 1) << 4;
#pragma unroll
    for (int ks = 0; ks < 4; ks++) {
        uint32_t a[2][4];
#pragma unroll
        for (int mt = 0; mt < 2; mt++) {
            uint32_t off = SWZ((uint32_t)((warpM + mt * 16 + arow) * 128 + ks * 32 + acol));
            ldmx4(a[mt], st + off);
        }
#pragma unroll
        for (int np = 0; np < 4; np++) {
            uint32_t bf[4];
            uint32_t off = SWZ((uint32_t)((warpN + np * 16 + brow) * 128 + ks * 32 + bcol));
            ldmx4(bf, st + 16384 + off);
#pragma unroll
            for (int mt = 0; mt < 2; mt++) {
                mma16816(acc[mt][np * 2],     a[mt], &bf[0]);
                mma16816(acc[mt][np * 2 + 1], a[mt], &bf[2]);
            }
        }
    }
}

__global__ __launch_bounds__(512, 1) void k_cheb_mma(int hop)
{
    extern __shared__ char smem[];
    const uint32_t sb = smem_to_u32(smem);
    const int tid = threadIdx.x;
    const int wid = tid >> 5;
    const int lane = tid & 31;
    const int row0 = blockIdx.x * 128;
    const int b = blockIdx.y;
    const int warpM = (wid & 3) * 32;
    const int warpN = (wid >> 2) * 64;

    const __half* A = g_sh + ((size_t)b * NN + row0) * NN;
    const __half* B = g_xth[hop] + (size_t)b * CC * NN;

    float acc[2][8][4];
#pragma unroll
    for (int i = 0; i < 2; i++)
#pragma unroll
        for (int j = 0; j < 8; j++)
#pragma unroll
            for (int q = 0; q < 4; q++) acc[i][j][q] = 0.f;

    cheb_load512(sb, 0, tid, A, B, 0);

    for (int s = 0; s < 16; s++) {
        CP_WAIT0();
        __syncthreads();
        if (s + 1 < 16)
            cheb_load512(sb, (s + 1) & 1, tid, A, B, (s + 1) * 64);
        hmma_stage512(sb + (s & 1) * CB_STAGE, warpM, warpN, lane, acc);
    }
    __syncthreads();   // protect smem reuse (transpose buffer)

    // ---------------- epilogue ----------------
    const int qr = lane >> 2;
    const int qc = (lane & 3) * 2;
    const size_t rmBase = (size_t)b * NN * CC;
    const __half* pH = (hop >= 1) ? g_xrh[hop - 1] : nullptr;
    const __half* pL = (hop >= 1) ? g_xrl[hop - 1] : nullptr;
    __half* oH = g_xrh[hop + 1];
    __half* oL = g_xrl[hop + 1];

    unsigned short* T = (unsigned short*)smem;   // [256][130] hi only

#pragma unroll
    for (int mt = 0; mt < 2; mt++)
#pragma unroll
        for (int half_ = 0; half_ < 2; half_++) {
            int rloc = warpM + mt * 16 + half_ * 8 + qr;
            int row = row0 + rloc;
#pragma unroll
            for (int nt = 0; nt < 8; nt++) {
                int col = warpN + nt * 8 + qc;
                float v0 = acc[mt][nt][half_ * 2 + 0];
                float v1 = acc[mt][nt][half_ * 2 + 1];
                size_t idx = rmBase + (size_t)row * CC + col;
                if (hop >= 1) {
                    __half2 phv = *(const __half2*)(pH + idx);
                    __half2 plv = *(const __half2*)(pL + idx);
                    v0 = 2.f * v0 - (__half2float(phv.x) + __half2float(plv.x));
                    v1 = 2.f * v1 - (__half2float(phv.y) + __half2float(plv.y));
                }
                __half h0 = __float2half(v0);
                __half l0 = __float2half(v0 - __half2float(h0));
                __half h1 = __float2half(v1);
                __half l1 = __float2half(v1 - __half2float(h1));
                *(__half2*)(oH + idx) = __half2(h0, h1);
                *(__half2*)(oL + idx) = __half2(l0, l1);
                if (hop < 2) {
                    T[(uint32_t)col * 130 + rloc]       = __half_as_ushort(h0);
                    T[(uint32_t)(col + 1) * 130 + rloc] = __half_as_ushort(h1);
                }
            }
        }

    if (hop < 2) {
        __syncthreads();
        __half* tH = g_xth[hop + 1] + (size_t)b * CC * NN;
#pragma unroll
        for (int i = 0; i < 32; i++) {
            int idx = tid + i * 512;           // over 256*64
            int c = idx >> 6;
            int j = idx & 63;
            // two adjacent rows of column c -> one aligned 32-bit word
            uint32_t w = *(const uint32_t*)&T[(uint32_t)c * 130 + 2 * j];
            *(uint32_t*)(tH + (size_t)c * NN + row0 + 2 * j) = w;
        }
    }
}

// =================== fp16 1-MMA gemm2 ====================================
// stage: A 16K | B 16K = 32K; x2 = 64K.
#define G2_STAGE 32768
#define G2_SMEM  (2 * G2_STAGE)

__global__ __launch_bounds__(256, 1) void k_gemm2_mma(const float* __restrict__ gc_b)
{
    extern __shared__ char smem[];
    const uint32_t sb = smem_to_u32(smem);
    const int tid = threadIdx.x;
    const int wid = tid >> 5;
    const int lane = tid & 31;
    const int row0 = blockIdx.x * 128;
    const int warpM = (wid & 3) * 32;
    const int warpN = (wid >> 2) * 64;

    float acc[2][8][4];
#pragma unroll
    for (int i = 0; i < 2; i++)
#pragma unroll
        for (int j = 0; j < 8; j++)
#pragma unroll
            for (int q = 0; q < 4; q++) acc[i][j][q] = 0.f;

    auto load = [&](int s, int buf) {
        const int m  = s >> 2;
        const int c0 = (s & 3) * 64;
        const __half* A = g_xrh[m] + (size_t)row0 * 256;
        const __half* B = g_wt + m * 32768;
        const uint32_t st = sb + buf * G2_STAGE;
#pragma unroll
        for (int i = 0; i < 4; i++) {
            int idx = tid + i * 256;
            int row = idx >> 3;
            int c16 = idx & 7;
            uint32_t off = SWZ((uint32_t)(row * 128 + c16 * 16));
            size_t src = (size_t)row * 256 + c0 + c16 * 8;
            CP16(st + off,         A + src);
            CP16(st + 16384 + off, B + src);
        }
        CP_COMMIT();
    };

    const int arow = lane & 15;
    const int acol = (lane >> 4) << 4;
    const int g    = lane >> 3;
    const int brow = ((g >> 1) << 3) + (lane & 7);
    const int bcol = (g & 1) << 4;

    load(0, 0);
    for (int s = 0; s < 16; s++) {
        CP_WAIT0();
        __syncthreads();
        if (s + 1 < 16) load(s + 1, (s + 1) & 1);
        const uint32_t st = sb + (s & 1) * G2_STAGE;
#pragma unroll
        for (int ks = 0; ks < 4; ks++) {
            uint32_t a[2][4];
#pragma unroll
            for (int mt = 0; mt < 2; mt++) {
                uint32_t off = SWZ((uint32_t)((warpM + mt * 16 + arow) * 128 + ks * 32 + acol));
                ldmx4(a[mt], st + off);
            }
#pragma unroll
            for (int np = 0; np < 4; np++) {
                uint32_t bf[4];
                uint32_t off = SWZ((uint32_t)((warpN + np * 16 + brow) * 128 + ks * 32 + bcol));
                ldmx4(bf, st + 16384 + off);
#pragma unroll
                for (int mt = 0; mt < 2; mt++) {
                    mma16816(acc[mt][np * 2],     a[mt], &bf[0]);
                    mma16816(acc[mt][np * 2 + 1], a[mt], &bf[2]);
                }
            }
        }
    }

    const int qr = lane >> 2;
    const int qc = (lane & 3) * 2;
#pragma unroll
    for (int mt = 0; mt < 2; mt++)
#pragma unroll
        for (int half_ = 0; half_ < 2; half_++) {
            int row = row0 + warpM + mt * 16 + half_ * 8 + qr;
#pragma unroll
            for (int nt = 0; nt < 8; nt++) {
                int col = warpN + nt * 8 + qc;
                float v0 = acc[mt][nt][half_ * 2 + 0] + gc_b[col];
                float v1 = acc[mt][nt][half_ * 2 + 1] + gc_b[col + 1];
                v0 = (v0 >= 0.f) ? v0 : 0.01f * v0;
                v1 = (v1 >= 0.f) ? v1 : 0.01f * v1;
                *(float2*)(g_gco + (size_t)row * 128 + col) = make_float2(v0, v1);
            }
        }
}

// ---------------- sa[b,k] reduction ---------------------------------------
__global__ __launch_bounds__(256) void k_sa(const float* __restrict__ hidden,
                                            const float* __restrict__ att_w,
                                            const float* __restrict__ att_b)
{
    const int k = blockIdx.x;
    const int b = blockIdx.y;
    const float* hb = hidden + ((size_t)(b * 4 + k) << 17);
    const int tid = threadIdx.x;

    float sum = 0.f;
    for (int i = tid; i < NN * HIDD; i += 256) {
        int n = i >> 6, h = i & 63;
        float re = hb[(n << 7) + h];
        float im = hb[(n << 7) + 64 + h];
        float c = g_cos[(k << 16) + i];
        float s = g_sin[(k << 16) + i];
        sum += (c * re - s * im) * att_w[(n << 7) + h]
             + (s * re + c * im) * att_w[(n << 7) + 64 + h];
    }
    __shared__ float red[8];
    for (int o = 16; o; o >>= 1) sum += __shfl_down_sync(0xffffffffu, sum, o);
    if ((tid & 31) == 0) red[tid >> 5] = sum;
    __syncthreads();
    if (tid < 8) {
        float v = red[tid];
        for (int o = 4; o; o >>= 1) v += __shfl_down_sync(0xffu, v, o);
        if (tid == 0) g_sa[b * 4 + k] = v + att_b[0];
    }
}

__global__ void k_softmax()
{
    int b = threadIdx.x;
    if (b >= BSZ) return;
    float s0 = g_sa[b * 4 + 0], s1 = g_sa[b * 4 + 1];
    float s2 = g_sa[b * 4 + 2], s3 = g_sa[b * 4 + 3];
    float m = fmaxf(fmaxf(s0, s1), fmaxf(s2, s3));
    float e0 = expf(s0 - m), e1 = expf(s1 - m), e2 = expf(s2 - m), e3 = expf(s3 - m);
    float inv = 1.f / (e0 + e1 + e2 + e3);
    g_wa[b * 4 + 0] = e0 * inv;
    g_wa[b * 4 + 1] = e1 * inv;
    g_wa[b * 4 + 2] = e2 * inv;
    g_wa[b * 4 + 3] = e3 * inv;
}

// ---------------- final: out = gco@W + b + att (att fused inline) ---------
__global__ __launch_bounds__(256) void k_final(const float* __restrict__ W,
                                               const float* __restrict__ bias,
                                               const float* __restrict__ hidden,
                                               float* __restrict__ out)
{
    const int row0 = blockIdx.x * 64;
    __shared__ float As[16][68];
    __shared__ float Bs[16][132];
    const int tid = threadIdx.x;
    const int a_r = tid >> 2;
    const int a_c = (tid & 3) << 2;
    const int b_r = tid >> 5;
    const int b_c = (tid & 31) << 2;
    const int ty  = tid >> 4;
    const int tx  = tid & 15;

    float acc[4][8];
#pragma unroll
    for (int i = 0; i < 4; i++)
#pragma unroll
        for (int j = 0; j < 8; j++) acc[i][j] = 0.f;

    for (int k0 = 0; k0 < 128; k0 += 16) {
        float4 av = *(const float4*)(g_gco + (size_t)(row0 + a_r) * 128 + k0 + a_c);
        float4 b0 = *(const float4*)(W + (size_t)(k0 + b_r) * 128 + b_c);
        float4 b1 = *(const float4*)(W + (size_t)(k0 + b_r + 8) * 128 + b_c);
        __syncthreads();
        As[a_c + 0][a_r] = av.x; As[a_c + 1][a_r] = av.y;
        As[a_c + 2][a_r] = av.z; As[a_c + 3][a_r] = av.w;
        *(float4*)&Bs[b_r][b_c]     = b0;
        *(float4*)&Bs[b_r + 8][b_c] = b1;
        __syncthreads();
#pragma unroll
        for (int kk = 0; kk < 16; kk++) {
            float ar[4], br[8];
            *(float4*)&ar[0] = *(const float4*)&As[kk][ty * 4];
            *(float4*)&br[0] = *(const float4*)&Bs[kk][tx * 8];
            *(float4*)&br[4] = *(const float4*)&Bs[kk][tx * 8 + 4];
#pragma unroll
            for (int i = 0; i < 4; i++)
#pragma unroll
                for (int j = 0; j < 8; j++) acc[i][j] += ar[i] * br[j];
        }
    }

    const bool isIm = (tx >= 8);
#pragma unroll
    for (int i = 0; i < 4; i++) {
        int rr = row0 + ty * 4 + i;
        int b  = rr >> 10;
        int n  = rr & 1023;
        size_t nh_off = (size_t)OUT0 + (((size_t)(b * 4 + 3) << 10 | n) << 7);
        float was[4] = {g_wa[b * 4 + 0], g_wa[b * 4 + 1],
                        g_wa[b * 4 + 2], g_wa[b * 4 + 3]};
#pragma unroll
        for (int j = 0; j < 8; j++) {
            int col = tx * 8 + j;
            int h = col & 63;
            float att = 0.f;
#pragma unroll
            for (int k = 0; k < 4; k++) {
                const float* hb = hidden + ((size_t)(b * 4 + k) << 17);
                float re = hb[(n << 7) + h];
                float im = hb[(n << 7) + 64 + h];
                float c = g_cos[(k << 16) + (n << 6) + h];
                float s = g_sin[(k << 16) + (n << 6) + h];
                float v = isIm ? (s * re + c * im) : (c * re - s * im);
                att += was[k] * v;
            }
            float v = acc[i][j] + bias[(size_t)n * 128 + col] + att;
            out[(size_t)rr * 128 + col] = v;
            out[nh_off + col]           = v;
        }
    }
}

__global__ __launch_bounds__(256) void k_copy(const float* __restrict__ hidden,
                                              float* __restrict__ out)
{
    int i4 = blockIdx.x * 256 + threadIdx.x;
    const int per_b = 3 * (NN * DD) / 4;
    if (i4 >= BSZ * per_b) return;
    int b  = i4 / per_b;
    int r4 = i4 - b * per_b;
    const float4* hv = (const float4*)hidden;
    float4* ov = (float4*)out;
    ov[(OUT0 / 4) + (size_t)b * 131072 + r4] = hv[(size_t)b * 131072 + 32768 + r4];
}

// ---------------- launch ---------------------------------------------------
extern "C" void kernel_launch(void* const* d_in, const int* in_sizes, int n_in,
                              void* d_out, int out_size)
{
    const float* inputs   = (const float*)d_in[0];
    const float* supports = (const float*)d_in[1];
    const float* hidden   = (const float*)d_in[2];
    const float* W        = (const float*)d_in[3];
    const float* bias     = (const float*)d_in[4];
    const float* R        = (const float*)d_in[5];
    const float* gc_w  = (const float*)d_in[6];
    const float* gc_b  = (const float*)d_in[7];
    const float* att_w = (const float*)d_in[10];
    const float* att_b = (const float*)d_in[11];
    float* out = (float*)d_out;

    static bool attrs_set = false;
    if (!attrs_set) {
        cudaFuncSetAttribute(k_cheb_mma, cudaFuncAttributeMaxDynamicSharedMemorySize, CB_SMEM);
        cudaFuncSetAttribute(k_gemm2_mma, cudaFuncAttributeMaxDynamicSharedMemorySize, G2_SMEM);
        attrs_set = true;
    }

    k_sconv<<<(BSZ * NN * NN / 4 + 255) / 256, 256>>>(supports);
    k_build_x0<<<dim3(NN / 32, CC / 32, BSZ), 256>>>(inputs, hidden);

    dim3 gC(8, BSZ);
    k_cheb_mma<<<gC, 512, CB_SMEM>>>(0);
    k_cheb_mma<<<gC, 512, CB_SMEM>>>(1);
    k_cheb_mma<<<gC, 512, CB_SMEM>>>(2);

    k_wt<<<(4 * 128 * 256 + 255) / 256, 256>>>(gc_w);
    k_cs<<<(PREK * NN * HIDD + 255) / 256, 256>>>(R);

    k_gemm2_mma<<<128, 256, G2_SMEM>>>(gc_b);

    k_sa<<<dim3(PREK, BSZ), 256>>>(hidden, att_w, att_b);
    k_softmax<<<1, 32>>>();

    k_final<<<(BSZ * NN) / 64, 256>>>(W, bias, hidden, out);
    k_copy<<<(BSZ * 3 * NN * DD / 4 + 255) / 256, 256>>>(hidden, out);
}